// round 11
// baseline (speedup 1.0000x reference)
#include <cuda_runtime.h>
#include <cuda_fp16.h>
#include <cstdint>

#define N_NODES 4096
#define FEAT    32
#define G3      192
#define HDIM    64
#define BATCH   4
#define TSTEPS  8
#define NBT     (BATCH*TSTEPS)           // 32
#define MAXD    128
#define NROWS   (NBT*N_NODES)            // 131072

// ---- gru mma kernel geometry ----
#define NP      64                        // nodes per block
#define GT      256                       // threads (8 warps = 2 m-groups x 4 col-groups)

// smem float offsets (gru)
#define O_B     0                         // B frags [6 k16][24 tiles][32 lanes][bh0 bh1 bl0 bl1]
#define O_AH    18432                     // A hi frags [6 k16][4 m16][32 lanes][4]
#define O_AL    21504                     // A lo frags
#define O_BIAS  24576                     // [256] r|z|ni|nh
#define O_WD    24832                     // [64]
#define O_HEAD  24896                     // [256] (q*64 + node)
#define SM_FLOATS 25152                   // 100608 bytes

// -------- static device scratch --------
__device__ int      g_row_len[N_NODES];
__device__ float    g_row_wsum[N_NODES];
__device__ int2     g_ell_cv[N_NODES * MAXD];
__device__ float    g_Wcomb[FEAT * G3];
__device__ float    g_bcomb[G3];
__device__ float    g_partN[64 * N_NODES];          // TRANSPOSED: [stat c][node n]
__device__ float    g_stat[64];                     // 0-31 sum, 32-63 sumsq
__device__ uint32_t g_xT2[(size_t)N_NODES * 16 * 32];  // [n][btp][f] half2=(bt, bt+16), 8MB
__device__ float    g_ya[(size_t)NROWS * FEAT];

// ============================================================
// helpers
// ============================================================
__device__ __forceinline__ float sigm(float v) { return __fdividef(1.0f, 1.0f + __expf(-v)); }
__device__ __forceinline__ float tanh_fast(float v) {
    const float e = __expf(-2.0f * v);
    return __fdividef(1.0f - e, 1.0f + e);
}
// pack two floats to f16x2 (first arg -> low half)
__device__ __forceinline__ uint32_t pack_f16x2(float lo_val, float hi_val) {
    uint32_t r;
    asm("cvt.rn.f16x2.f32 %0, %1, %2;" : "=r"(r) : "f"(hi_val), "f"(lo_val));
    return r;
}
__device__ __forceinline__ void mma16(float* d, const uint4& a, const uint2& b) {
    asm volatile(
        "mma.sync.aligned.m16n8k16.row.col.f32.f16.f16.f32 "
        "{%0,%1,%2,%3}, {%4,%5,%6,%7}, {%8,%9}, {%0,%1,%2,%3};"
        : "+f"(d[0]), "+f"(d[1]), "+f"(d[2]), "+f"(d[3])
        : "r"(a.x), "r"(a.y), "r"(a.z), "r"(a.w), "r"(b.x), "r"(b.y));
}

// ============================================================
// Kernel 1 (fused prep): blocks [0,512)   -> dense adj -> packed ELL
//                        blocks [512,4608)-> transpose x (fp16x2) + BN partials
// ============================================================
__global__ void __launch_bounds__(256)
prep_kernel(const float* __restrict__ adj, const float* __restrict__ x)
{
    const int tid  = threadIdx.x;
    const int lane = tid & 31;
    const int w    = tid >> 5;

    if (blockIdx.x < 512) {
        // ---------- ELL build: warp = one adjacency row, MLP=8 ----------
        const int warp = blockIdx.x * 8 + w;
        const float* row = adj + (size_t)warp * N_NODES;
        const int base = warp * MAXD;
        int cnt = 0; float wsum = 0.f;
        #pragma unroll 1
        for (int g = 0; g < N_NODES / 256; ++g) {
            float v[8];
            #pragma unroll
            for (int j = 0; j < 8; ++j) v[j] = row[g * 256 + j * 32 + lane];
            #pragma unroll
            for (int j = 0; j < 8; ++j) {
                const int c = g * 256 + j * 32 + lane;
                wsum += v[j];
                const unsigned mask = __ballot_sync(0xffffffffu, v[j] != 0.0f);
                if (v[j] != 0.0f) {
                    const int pos = cnt + __popc(mask & ((1u << lane) - 1u));
                    if (pos < MAXD) g_ell_cv[base + pos] = make_int2(c, __float_as_int(v[j]));
                }
                cnt += __popc(mask);
            }
        }
        #pragma unroll
        for (int o = 16; o > 0; o >>= 1) wsum += __shfl_xor_sync(0xffffffffu, wsum, o);
        if (lane == 0) {
            g_row_len[warp]  = cnt < MAXD ? cnt : MAXD;
            g_row_wsum[warp] = wsum;
        }
    } else {
        // ---------- transpose to fp16x2 + per-node BN partials ----------
        const int n   = blockIdx.x - 512;
        const int bt  = tid >> 3;
        const int f0  = (tid & 7) * 4;

        __shared__ float sh[8][64];
        __shared__ float xbuf[32][32];

        const float4 v = *(const float4*)(x + ((size_t)bt * N_NODES + n) * FEAT + f0);
        *(float4*)&xbuf[bt][f0] = v;

        float s0 = v.x, s1 = v.y, s2 = v.z, s3 = v.w;
        float q0 = v.x * v.x, q1 = v.y * v.y, q2 = v.z * v.z, q3 = v.w * v.w;
        #pragma unroll
        for (int o = 8; o <= 16; o <<= 1) {
            s0 += __shfl_xor_sync(0xffffffffu, s0, o);
            s1 += __shfl_xor_sync(0xffffffffu, s1, o);
            s2 += __shfl_xor_sync(0xffffffffu, s2, o);
            s3 += __shfl_xor_sync(0xffffffffu, s3, o);
            q0 += __shfl_xor_sync(0xffffffffu, q0, o);
            q1 += __shfl_xor_sync(0xffffffffu, q1, o);
            q2 += __shfl_xor_sync(0xffffffffu, q2, o);
            q3 += __shfl_xor_sync(0xffffffffu, q3, o);
        }
        if (lane < 8) {
            sh[w][f0 + 0]      = s0;  sh[w][f0 + 1]      = s1;
            sh[w][f0 + 2]      = s2;  sh[w][f0 + 3]      = s3;
            sh[w][32 + f0 + 0] = q0;  sh[w][32 + f0 + 1] = q1;
            sh[w][32 + f0 + 2] = q2;  sh[w][32 + f0 + 3] = q3;
        }
        __syncthreads();
        if (tid < 64) {
            float a = 0.f;
            #pragma unroll
            for (int i = 0; i < 8; ++i) a += sh[i][tid];
            g_partN[tid * N_NODES + n] = a;     // transposed layout
        }
        if (tid < 128) {
            const int btp = tid >> 3;
            const int fq  = (tid & 7) * 4;
            const float4 a = *(const float4*)&xbuf[btp][fq];
            const float4 b = *(const float4*)&xbuf[btp + 16][fq];
            uint4 wv;
            wv.x = pack_f16x2(a.x, b.x);
            wv.y = pack_f16x2(a.y, b.y);
            wv.z = pack_f16x2(a.z, b.z);
            wv.w = pack_f16x2(a.w, b.w);
            *(uint4*)&g_xT2[((size_t)n * 16 + btp) * 32 + fq] = wv;
        }
    }
}

// ============================================================
// Kernel 2 (parallel finalize): blocks 0-63  -> stat column reduce
//                               blocks 64-87 -> Wcomb, block 88 -> bcomb
// ============================================================
__global__ void __launch_bounds__(256)
finalize_kernel(const float* __restrict__ Wgcn,
                const float* __restrict__ bgcn,
                const float* __restrict__ Wih,
                const float* __restrict__ bih)
{
    const int tid = threadIdx.x;
    const int bid = blockIdx.x;

    if (bid < 64) {
        __shared__ float red[256];
        const float* p = g_partN + bid * N_NODES;
        float a = 0.f;
        #pragma unroll 4
        for (int i = tid; i < N_NODES; i += 256) a += p[i];
        red[tid] = a;
        __syncthreads();
        #pragma unroll
        for (int s = 128; s > 0; s >>= 1) {
            if (tid < s) red[tid] += red[tid + s];
            __syncthreads();
        }
        if (tid == 0) g_stat[bid] = red[0];
    } else if (bid < 88) {
        const int idx = (bid - 64) * 256 + tid;   // < 6144
        const int f = idx / G3, j = idx % G3;
        float acc = 0.f;
        #pragma unroll 8
        for (int c = 0; c < 32; ++c) acc += Wgcn[f * 32 + c] * Wih[c * G3 + j];
        g_Wcomb[idx] = acc;
    } else {
        if (tid < G3) {
            float acc = bih[tid];
            #pragma unroll 8
            for (int c = 0; c < 32; ++c) acc += bgcn[c] * Wih[c * G3 + tid];
            g_bcomb[tid] = acc;
        }
    }
}

// ============================================================
// Kernel 3: aggregation (one block = one node, all 32 bt), fp16 x
// unroll 8 neighbors -> 16 half2 loads in flight
// ============================================================
__global__ void __launch_bounds__(256)
agg_kernel(const float* __restrict__ gamma, const float* __restrict__ beta)
{
    const int m   = blockIdx.x;
    const int tid = threadIdx.x;
    const int f   = tid & 31;
    const int bt0 = tid >> 5;

    const int len = g_row_len[m];
    const float wsum = g_row_wsum[m];
    const int2* cv = g_ell_cv + m * MAXD;

    float a0 = 0.f, a1 = 0.f, a2 = 0.f, a3 = 0.f;
    const int off = bt0 * 32 + f;

    int k = 0;
    for (; k + 7 < len; k += 8) {
        int2 e[8];
        #pragma unroll
        for (int j = 0; j < 8; ++j) e[j] = cv[k + j];
        uint32_t r0[8], r1[8];
        #pragma unroll
        for (int j = 0; j < 8; ++j) {
            const uint32_t* p = g_xT2 + (size_t)e[j].x * 512 + off;
            r0[j] = p[0];
            r1[j] = p[256];
        }
        #pragma unroll
        for (int j = 0; j < 8; ++j) {
            const float w = __int_as_float(e[j].y);
            const float2 u0 = __half22float2(*(const __half2*)&r0[j]);
            const float2 u1 = __half22float2(*(const __half2*)&r1[j]);
            a0 += w * u0.x; a2 += w * u0.y; a1 += w * u1.x; a3 += w * u1.y;
        }
    }
    for (; k < len; ++k) {
        const int2 e = cv[k];
        const float w = __int_as_float(e.y);
        const uint32_t* p = g_xT2 + (size_t)e.x * 512 + off;
        const float2 u0 = __half22float2(*(const __half2*)&p[0]);
        const float2 u1 = __half22float2(*(const __half2*)&p[256]);
        a0 += w * u0.x; a2 += w * u0.y; a1 += w * u1.x; a3 += w * u1.y;
    }

    const float M    = (float)NROWS;
    const float mean = g_stat[f] / M;
    const float var  = g_stat[32 + f] / M - mean * mean;
    const float A    = gamma[f] * rsqrtf(var + 1e-5f);
    const float C    = (beta[f] - mean * A) * wsum;
    g_ya[((size_t)(bt0 +  0) * N_NODES + m) * FEAT + f] = A * a0 + C;
    g_ya[((size_t)(bt0 +  8) * N_NODES + m) * FEAT + f] = A * a1 + C;
    g_ya[((size_t)(bt0 + 16) * N_NODES + m) * FEAT + f] = A * a2 + C;
    g_ya[((size_t)(bt0 + 24) * N_NODES + m) * FEAT + f] = A * a3 + C;
}

// ============================================================
// Kernel 4: GRU scan via mma.sync m16n8k16 fp16 (3-term split).
// block = 64 nodes x 1 batch, 256 threads, 2 blocks/SM, grid 256.
// warp = (m-group mq: 2 m16 tiles) x (col-group q: 16 hd cols).
// Register-diet epilogue: h_prev reconstructed from A fragments
// (hi+lo fp16, err ~2^-22) instead of 16 persistent registers;
// ya staged via transient LDG inside the epilogue phase.
// ============================================================
#define GK16(C, ACCN)                                                             \
{                                                                                 \
    const uint4 ah0 = *(const uint4*)&sAh[(((C) * 4 + mq * 2    ) * 32 + lane) * 4]; \
    const uint4 al0 = *(const uint4*)&sAl[(((C) * 4 + mq * 2    ) * 32 + lane) * 4]; \
    const uint4 ah1 = *(const uint4*)&sAh[(((C) * 4 + mq * 2 + 1) * 32 + lane) * 4]; \
    const uint4 al1 = *(const uint4*)&sAl[(((C) * 4 + mq * 2 + 1) * 32 + lane) * 4]; \
    _Pragma("unroll")                                                             \
    for (int tt = 0; tt < 6; ++tt) {                                              \
        const uint4 bq = *(const uint4*)&sB[(((C) * 24 + tbase + tt) * 32 + lane) * 4]; \
        const uint2 bh = make_uint2(bq.x, bq.y);                                  \
        const uint2 bl = make_uint2(bq.z, bq.w);                                  \
        float* c0p; float* c1p;                                                   \
        if (tt < 4) { c0p = accRZ[0][tt];     c1p = accRZ[1][tt];     }           \
        else        { c0p = ACCN[0][tt - 4];  c1p = ACCN[1][tt - 4];  }           \
        mma16(c0p, ah0, bh); mma16(c0p, al0, bh); mma16(c0p, ah0, bl);            \
        mma16(c1p, ah1, bh); mma16(c1p, al1, bh); mma16(c1p, ah1, bl);            \
    }                                                                             \
}

__global__ void __launch_bounds__(GT, 2)
gru_mma_kernel(const float* __restrict__ Whh,
               const float* __restrict__ bhh,
               const float* __restrict__ Wd,
               const float* __restrict__ bd,
               float* __restrict__ out)
{
    extern __shared__ float sm[];
    float* sB    = sm + O_B;
    float* sAh   = sm + O_AH;
    float* sAl   = sm + O_AL;
    float* sBias = sm + O_BIAS;
    float* sWd   = sm + O_WD;
    float* sHead = sm + O_HEAD;

    const int tid  = threadIdx.x;
    const int wid  = tid >> 5;
    const int lane = tid & 31;
    const int mq   = wid >> 2;          // m-group 0..1 (m16 tiles mq*2, mq*2+1)
    const int q    = wid & 3;           // col-group 0..3 (hd in [q*16, q*16+16))
    const int tbase = q * 6;

    const int b   = blockIdx.x >> 6;
    const int gm0 = (blockIdx.x & 63) * NP;

    // ---- zero A fragment regions (h0 = 0) ----
    for (int i = tid; i < 3072; i += GT) { sAh[i] = 0.0f; sAl[i] = 0.0f; }

    // ---- stage B fragments (fp16 hi/lo, q-major tile order) ----
    {
        __half* pB = (__half*)sB;
        for (int idx = tid; idx < 96 * G3; idx += GT) {
            const int k = idx / G3, n = idx % G3;
            const float w = (k < 32) ? g_Wcomb[k * G3 + n] : Whh[(k - 32) * G3 + n];
            const __half hh = __float2half_rn(w);
            const __half hl = __float2half_rn(w - __half2float(hh));
            const int g    = n >> 6;
            const int hd   = n & 63;
            const int j    = hd >> 3;
            const int qq   = j >> 1;
            const int sub  = j & 1;
            const int tile = qq * 6 + g * 2 + sub;
            const int ccol = hd & 7;
            const int chunk = k >> 4;
            const int rem   = k & 15;
            const int lt    = ccol * 4 + ((rem & 7) >> 1);
            const int regB  = (rem >= 8) ? 1 : 0;
            const int hb    = rem & 1;
            const int base  = ((chunk * 24 + tile) * 32 + lt) * 4;
            pB[(base + regB) * 2 + hb]     = hh;
            pB[(base + 2 + regB) * 2 + hb] = hl;
        }
    }
    if (tid < HDIM) {
        sBias[tid]       = g_bcomb[tid]       + bhh[tid];        // r
        sBias[64 + tid]  = g_bcomb[64 + tid]  + bhh[64 + tid];   // z
        sBias[128 + tid] = g_bcomb[128 + tid];                   // n_i
        sBias[192 + tid] = bhh[128 + tid];                       // n_h
        sWd[tid]         = Wd[tid];
    }
    const float bdv = bd[0];

    // ---- epilogue geometry ----
    const int gr = lane >> 2;
    const int c0 = (lane & 3) * 2;

    // ---- ya staging geometry ----
    const int nodeS = tid >> 2;           // 0..63
    const int fc    = tid & 3;            // feature chunk: f base = fc*8
    const int baseS = (((fc >> 1) * 4 + (nodeS >> 4)) * 32 + (nodeS & 7) * 4) * 4
                      + ((fc & 1) ? 2 : 0) + (((nodeS & 15) >= 8) ? 1 : 0);

    // ---- stage ya_0 ----
    {
        const float* p = g_ya + ((size_t)(b * TSTEPS) * N_NODES + gm0 + nodeS) * FEAT + fc * 8;
        const float4 q0 = *(const float4*)(p);
        const float4 q1 = *(const float4*)(p + 4);
        float v[8];
        *(float4*)(v) = q0; *(float4*)(v + 4) = q1;
        #pragma unroll
        for (int j = 0; j < 4; ++j) {
            const float a = v[2 * j], bb = v[2 * j + 1];
            const __half ha = __float2half_rn(a);
            const __half hb = __float2half_rn(bb);
            sAh[baseS + j * 4] = __uint_as_float(pack_f16x2(a, bb));
            sAl[baseS + j * 4] = __uint_as_float(pack_f16x2(a - __half2float(ha),
                                                            bb - __half2float(hb)));
        }
    }
    __syncthreads();

    for (int t8 = 0; t8 < TSTEPS; ++t8) {
        // ---- accumulators ----
        float accRZ[2][4][4], accNi[2][2][4], accNh[2][2][4];
        #pragma unroll
        for (int m = 0; m < 2; ++m) {
            #pragma unroll
            for (int t = 0; t < 4; ++t)
                #pragma unroll
                for (int s = 0; s < 4; ++s) accRZ[m][t][s] = 0.0f;
            #pragma unroll
            for (int t = 0; t < 2; ++t)
                #pragma unroll
                for (int s = 0; s < 4; ++s) { accNi[m][t][s] = 0.0f; accNh[m][t][s] = 0.0f; }
        }

        GK16(0, accNi) GK16(1, accNi)
        GK16(2, accNh) GK16(3, accNh) GK16(4, accNh) GK16(5, accNh)

        __syncthreads();   // all warps done reading A frags (ya_t + h_t)

        // ---- transient ya_{t+1} load (issued early, consumed at epilogue end) ----
        float4 pf0, pf1;
        if (t8 + 1 < TSTEPS) {
            const float* p = g_ya + ((size_t)(b * TSTEPS + t8 + 1) * N_NODES + gm0 + nodeS) * FEAT + fc * 8;
            pf0 = *(const float4*)(p);
            pf1 = *(const float4*)(p + 4);
        }

        // ---- register epilogue (h_prev reconstructed from frags) ----
        float hp[2][2] = {{0.f, 0.f}, {0.f, 0.f}};
        #pragma unroll
        for (int m = 0; m < 2; ++m) {
            const int base = (((2 + q) * 4 + mq * 2 + m) * 32 + lane) * 4;
            const uint4 hh4 = *(const uint4*)&sAh[base];
            const uint4 hl4 = *(const uint4*)&sAl[base];
            uint32_t hhout[4], hlout[4];
            #pragma unroll
            for (int sub = 0; sub < 2; ++sub) {
                float hv[4];
                #pragma unroll
                for (int s = 0; s < 4; ++s) {
                    const int hd = q * 16 + sub * 8 + c0 + (s & 1);
                    // reconstruct h_prev = hi + lo
                    const uint32_t wH = ((const uint32_t*)&hh4)[sub * 2 + (s >> 1)];
                    const uint32_t wL = ((const uint32_t*)&hl4)[sub * 2 + (s >> 1)];
                    const __half2 h2H = *(const __half2*)&wH;
                    const __half2 h2L = *(const __half2*)&wL;
                    const float hpv = ((s & 1) ? __half2float(__high2half(h2H)) + __half2float(__high2half(h2L))
                                               : __half2float(__low2half(h2H))  + __half2float(__low2half(h2L)));
                    const float r = sigm(accRZ[m][sub][s]     + sBias[hd]);
                    const float z = sigm(accRZ[m][2 + sub][s] + sBias[64 + hd]);
                    const float n = tanh_fast(accNi[m][sub][s] + sBias[128 + hd]
                                              + r * (accNh[m][sub][s] + sBias[192 + hd]));
                    hv[s] = (1.0f - z) * n + z * hpv;
                    hp[m][s >> 1] += hv[s] * sWd[hd];
                }
                hhout[sub * 2]     = pack_f16x2(hv[0], hv[1]);
                hhout[sub * 2 + 1] = pack_f16x2(hv[2], hv[3]);
                const __half a0 = __float2half_rn(hv[0]);
                const __half a1 = __float2half_rn(hv[1]);
                const __half a2 = __float2half_rn(hv[2]);
                const __half a3 = __float2half_rn(hv[3]);
                hlout[sub * 2]     = pack_f16x2(hv[0] - __half2float(a0), hv[1] - __half2float(a1));
                hlout[sub * 2 + 1] = pack_f16x2(hv[2] - __half2float(a2), hv[3] - __half2float(a3));
            }
            *(uint4*)&sAh[base] = *(const uint4*)hhout;
            *(uint4*)&sAl[base] = *(const uint4*)hlout;
        }

        // ---- stage ya_{t+1} (chunks 0-1, disjoint from h chunks 2-5) ----
        if (t8 + 1 < TSTEPS) {
            float v[8];
            *(float4*)(v) = pf0; *(float4*)(v + 4) = pf1;
            #pragma unroll
            for (int j = 0; j < 4; ++j) {
                const float a = v[2 * j], bb = v[2 * j + 1];
                const __half ha = __float2half_rn(a);
                const __half hb = __float2half_rn(bb);
                sAh[baseS + j * 4] = __uint_as_float(pack_f16x2(a, bb));
                sAl[baseS + j * 4] = __uint_as_float(pack_f16x2(a - __half2float(ha),
                                                                bb - __half2float(hb)));
            }
        }

        // ---- head reduce across the 4 lanes sharing gr ----
        #pragma unroll
        for (int m = 0; m < 2; ++m) {
            hp[m][0] += __shfl_xor_sync(0xffffffffu, hp[m][0], 1);
            hp[m][0] += __shfl_xor_sync(0xffffffffu, hp[m][0], 2);
            hp[m][1] += __shfl_xor_sync(0xffffffffu, hp[m][1], 1);
            hp[m][1] += __shfl_xor_sync(0xffffffffu, hp[m][1], 2);
        }
        if ((lane & 3) == 0) {
            #pragma unroll
            for (int m = 0; m < 2; ++m) {
                const int node = (mq * 2 + m) * 16 + gr;
                sHead[q * 64 + node]     = hp[m][0];
                sHead[q * 64 + node + 8] = hp[m][1];
            }
        }
        __syncthreads();   // h frags + ya frags + sHead complete

        if (tid < NP) {
            out[(size_t)(b * TSTEPS + t8) * N_NODES + gm0 + tid] =
                bdv + sHead[tid] + sHead[64 + tid] + sHead[128 + tid] + sHead[192 + tid];
        }
        // out STG overlaps the next iteration's GEMM (no barrier between).
    }
}

// ============================================================
// launch
// ============================================================
extern "C" void kernel_launch(void* const* d_in, const int* in_sizes, int n_in,
                              void* d_out, int out_size)
{
    const float* x     = (const float*)d_in[0];
    const float* adj   = (const float*)d_in[1];
    const float* gamma = (const float*)d_in[2];
    const float* beta  = (const float*)d_in[3];
    const float* Wgcn  = (const float*)d_in[4];
    const float* bgcn  = (const float*)d_in[5];
    const float* Wih   = (const float*)d_in[6];
    const float* Whh   = (const float*)d_in[7];
    const float* bih   = (const float*)d_in[8];
    const float* bhh   = (const float*)d_in[9];
    const float* Wd    = (const float*)d_in[10];
    const float* bd    = (const float*)d_in[11];
    float* out = (float*)d_out;

    const int smem_bytes = SM_FLOATS * (int)sizeof(float);   // 100608
    cudaFuncSetAttribute(gru_mma_kernel, cudaFuncAttributeMaxDynamicSharedMemorySize, smem_bytes);

    prep_kernel<<<512 + N_NODES, 256>>>(adj, x);
    finalize_kernel<<<89, 256>>>(Wgcn, bgcn, Wih, bih);
    agg_kernel<<<N_NODES, 256>>>(gamma, beta);
    gru_mma_kernel<<<BATCH * (N_NODES / NP), GT, smem_bytes>>>(Whh, bhh, Wd, bd, out);
}

// round 12
// speedup vs baseline: 1.4324x; 1.4324x over previous
#include <cuda_runtime.h>
#include <cuda_fp16.h>
#include <cstdint>

#define N_NODES 4096
#define FEAT    32
#define G3      192
#define HDIM    64
#define BATCH   4
#define TSTEPS  8
#define NBT     (BATCH*TSTEPS)           // 32
#define MAXD    128
#define NROWS   (NBT*N_NODES)            // 131072

// ---- gru mma kernel geometry ----
#define NP      64                        // nodes per block
#define GT      256                       // threads (8 warps = 2 m-groups x 4 col-groups)

// smem float offsets (gru)
#define O_B     0                         // B frags [6 k16][24 tiles][32 lanes][bh0 bh1 bl0 bl1]
#define O_AH    18432                     // A hi frags [6 k16][4 m16][32 lanes][4]
#define O_AL    21504                     // A lo frags
#define O_BIAS  24576                     // [256] r|z|ni|nh
#define O_WD    24832                     // [64]
#define O_HEAD  24896                     // [256] (q*64 + node)
#define SM_FLOATS 25152                   // 100608 bytes

// -------- static device scratch --------
__device__ int      g_row_len[N_NODES];
__device__ float    g_row_wsum[N_NODES];
__device__ int2     g_ell_cv[N_NODES * MAXD];
__device__ float    g_Wcomb[FEAT * G3];
__device__ float    g_bcomb[G3];
__device__ float    g_partN[64 * N_NODES];          // TRANSPOSED: [stat c][node n]
__device__ float    g_stat[64];                     // 0-31 sum, 32-63 sumsq
__device__ uint32_t g_xT2[(size_t)N_NODES * 16 * 32];  // [n][btp][f] half2=(bt, bt+16), 8MB
__device__ float    g_ya[(size_t)NROWS * FEAT];

// ============================================================
// helpers
// ============================================================
__device__ __forceinline__ float sigm(float v) { return __fdividef(1.0f, 1.0f + __expf(-v)); }
__device__ __forceinline__ float tanh_fast(float v) {
    const float e = __expf(-2.0f * v);
    return __fdividef(1.0f - e, 1.0f + e);
}
// pack two floats to f16x2 (first arg -> low half)
__device__ __forceinline__ uint32_t pack_f16x2(float lo_val, float hi_val) {
    uint32_t r;
    asm("cvt.rn.f16x2.f32 %0, %1, %2;" : "=r"(r) : "f"(hi_val), "f"(lo_val));
    return r;
}
__device__ __forceinline__ void mma16(float* d, const uint4& a, const uint2& b) {
    asm volatile(
        "mma.sync.aligned.m16n8k16.row.col.f32.f16.f16.f32 "
        "{%0,%1,%2,%3}, {%4,%5,%6,%7}, {%8,%9}, {%0,%1,%2,%3};"
        : "+f"(d[0]), "+f"(d[1]), "+f"(d[2]), "+f"(d[3])
        : "r"(a.x), "r"(a.y), "r"(a.z), "r"(a.w), "r"(b.x), "r"(b.y));
}

// ============================================================
// Kernel 1 (fused prep): blocks [0,512)   -> dense adj -> packed ELL
//                        blocks [512,4608)-> transpose x (fp16x2) + BN partials
// ============================================================
__global__ void __launch_bounds__(256)
prep_kernel(const float* __restrict__ adj, const float* __restrict__ x)
{
    const int tid  = threadIdx.x;
    const int lane = tid & 31;
    const int w    = tid >> 5;

    if (blockIdx.x < 512) {
        // ---------- ELL build: warp = one adjacency row, MLP=8 ----------
        const int warp = blockIdx.x * 8 + w;
        const float* row = adj + (size_t)warp * N_NODES;
        const int base = warp * MAXD;
        int cnt = 0; float wsum = 0.f;
        #pragma unroll 1
        for (int g = 0; g < N_NODES / 256; ++g) {
            float v[8];
            #pragma unroll
            for (int j = 0; j < 8; ++j) v[j] = row[g * 256 + j * 32 + lane];
            #pragma unroll
            for (int j = 0; j < 8; ++j) {
                const int c = g * 256 + j * 32 + lane;
                wsum += v[j];
                const unsigned mask = __ballot_sync(0xffffffffu, v[j] != 0.0f);
                if (v[j] != 0.0f) {
                    const int pos = cnt + __popc(mask & ((1u << lane) - 1u));
                    if (pos < MAXD) g_ell_cv[base + pos] = make_int2(c, __float_as_int(v[j]));
                }
                cnt += __popc(mask);
            }
        }
        #pragma unroll
        for (int o = 16; o > 0; o >>= 1) wsum += __shfl_xor_sync(0xffffffffu, wsum, o);
        if (lane == 0) {
            g_row_len[warp]  = cnt < MAXD ? cnt : MAXD;
            g_row_wsum[warp] = wsum;
        }
    } else {
        // ---------- transpose to fp16x2 + per-node BN partials ----------
        const int n   = blockIdx.x - 512;
        const int bt  = tid >> 3;
        const int f0  = (tid & 7) * 4;

        __shared__ float sh[8][64];
        __shared__ float xbuf[32][32];

        const float4 v = *(const float4*)(x + ((size_t)bt * N_NODES + n) * FEAT + f0);
        *(float4*)&xbuf[bt][f0] = v;

        float s0 = v.x, s1 = v.y, s2 = v.z, s3 = v.w;
        float q0 = v.x * v.x, q1 = v.y * v.y, q2 = v.z * v.z, q3 = v.w * v.w;
        #pragma unroll
        for (int o = 8; o <= 16; o <<= 1) {
            s0 += __shfl_xor_sync(0xffffffffu, s0, o);
            s1 += __shfl_xor_sync(0xffffffffu, s1, o);
            s2 += __shfl_xor_sync(0xffffffffu, s2, o);
            s3 += __shfl_xor_sync(0xffffffffu, s3, o);
            q0 += __shfl_xor_sync(0xffffffffu, q0, o);
            q1 += __shfl_xor_sync(0xffffffffu, q1, o);
            q2 += __shfl_xor_sync(0xffffffffu, q2, o);
            q3 += __shfl_xor_sync(0xffffffffu, q3, o);
        }
        if (lane < 8) {
            sh[w][f0 + 0]      = s0;  sh[w][f0 + 1]      = s1;
            sh[w][f0 + 2]      = s2;  sh[w][f0 + 3]      = s3;
            sh[w][32 + f0 + 0] = q0;  sh[w][32 + f0 + 1] = q1;
            sh[w][32 + f0 + 2] = q2;  sh[w][32 + f0 + 3] = q3;
        }
        __syncthreads();
        if (tid < 64) {
            float a = 0.f;
            #pragma unroll
            for (int i = 0; i < 8; ++i) a += sh[i][tid];
            g_partN[tid * N_NODES + n] = a;     // transposed layout
        }
        if (tid < 128) {
            const int btp = tid >> 3;
            const int fq  = (tid & 7) * 4;
            const float4 a = *(const float4*)&xbuf[btp][fq];
            const float4 b = *(const float4*)&xbuf[btp + 16][fq];
            uint4 wv;
            wv.x = pack_f16x2(a.x, b.x);
            wv.y = pack_f16x2(a.y, b.y);
            wv.z = pack_f16x2(a.z, b.z);
            wv.w = pack_f16x2(a.w, b.w);
            *(uint4*)&g_xT2[((size_t)n * 16 + btp) * 32 + fq] = wv;
        }
    }
}

// ============================================================
// Kernel 2 (parallel finalize): blocks 0-63  -> stat column reduce
//                               blocks 64-87 -> Wcomb, block 88 -> bcomb
// ============================================================
__global__ void __launch_bounds__(256)
finalize_kernel(const float* __restrict__ Wgcn,
                const float* __restrict__ bgcn,
                const float* __restrict__ Wih,
                const float* __restrict__ bih)
{
    const int tid = threadIdx.x;
    const int bid = blockIdx.x;

    if (bid < 64) {
        __shared__ float red[256];
        const float* p = g_partN + bid * N_NODES;
        float a = 0.f;
        #pragma unroll 4
        for (int i = tid; i < N_NODES; i += 256) a += p[i];
        red[tid] = a;
        __syncthreads();
        #pragma unroll
        for (int s = 128; s > 0; s >>= 1) {
            if (tid < s) red[tid] += red[tid + s];
            __syncthreads();
        }
        if (tid == 0) g_stat[bid] = red[0];
    } else if (bid < 88) {
        const int idx = (bid - 64) * 256 + tid;   // < 6144
        const int f = idx / G3, j = idx % G3;
        float acc = 0.f;
        #pragma unroll 8
        for (int c = 0; c < 32; ++c) acc += Wgcn[f * 32 + c] * Wih[c * G3 + j];
        g_Wcomb[idx] = acc;
    } else {
        if (tid < G3) {
            float acc = bih[tid];
            #pragma unroll 8
            for (int c = 0; c < 32; ++c) acc += bgcn[c] * Wih[c * G3 + tid];
            g_bcomb[tid] = acc;
        }
    }
}

// ============================================================
// Kernel 3: aggregation (one block = one node, all 32 bt), fp16 x
// unroll 4 neighbors (R10 config: 32 regs, 8 blocks/SM)
// ============================================================
__global__ void __launch_bounds__(256)
agg_kernel(const float* __restrict__ gamma, const float* __restrict__ beta)
{
    const int m   = blockIdx.x;
    const int tid = threadIdx.x;
    const int f   = tid & 31;
    const int bt0 = tid >> 5;

    const int len = g_row_len[m];
    const float wsum = g_row_wsum[m];
    const int2* cv = g_ell_cv + m * MAXD;

    float a0 = 0.f, a1 = 0.f, a2 = 0.f, a3 = 0.f;
    const int off = bt0 * 32 + f;

    int k = 0;
    for (; k + 3 < len; k += 4) {
        const int2 e0 = cv[k], e1 = cv[k + 1], e2 = cv[k + 2], e3 = cv[k + 3];
        const float w0 = __int_as_float(e0.y), w1 = __int_as_float(e1.y);
        const float w2 = __int_as_float(e2.y), w3 = __int_as_float(e3.y);
        const uint32_t* p0 = g_xT2 + (size_t)e0.x * 512 + off;
        const uint32_t* p1 = g_xT2 + (size_t)e1.x * 512 + off;
        const uint32_t* p2 = g_xT2 + (size_t)e2.x * 512 + off;
        const uint32_t* p3 = g_xT2 + (size_t)e3.x * 512 + off;
        const uint32_t r00 = p0[0], r01 = p0[256];
        const uint32_t r10 = p1[0], r11 = p1[256];
        const uint32_t r20 = p2[0], r21 = p2[256];
        const uint32_t r30 = p3[0], r31 = p3[256];
        {
            const float2 u0 = __half22float2(*(const __half2*)&r00);
            const float2 u1 = __half22float2(*(const __half2*)&r01);
            a0 += w0 * u0.x; a2 += w0 * u0.y; a1 += w0 * u1.x; a3 += w0 * u1.y;
        }
        {
            const float2 u0 = __half22float2(*(const __half2*)&r10);
            const float2 u1 = __half22float2(*(const __half2*)&r11);
            a0 += w1 * u0.x; a2 += w1 * u0.y; a1 += w1 * u1.x; a3 += w1 * u1.y;
        }
        {
            const float2 u0 = __half22float2(*(const __half2*)&r20);
            const float2 u1 = __half22float2(*(const __half2*)&r21);
            a0 += w2 * u0.x; a2 += w2 * u0.y; a1 += w2 * u1.x; a3 += w2 * u1.y;
        }
        {
            const float2 u0 = __half22float2(*(const __half2*)&r30);
            const float2 u1 = __half22float2(*(const __half2*)&r31);
            a0 += w3 * u0.x; a2 += w3 * u0.y; a1 += w3 * u1.x; a3 += w3 * u1.y;
        }
    }
    for (; k < len; ++k) {
        const int2 e = cv[k];
        const float w = __int_as_float(e.y);
        const uint32_t* p = g_xT2 + (size_t)e.x * 512 + off;
        const float2 u0 = __half22float2(*(const __half2*)&p[0]);
        const float2 u1 = __half22float2(*(const __half2*)&p[256]);
        a0 += w * u0.x; a2 += w * u0.y; a1 += w * u1.x; a3 += w * u1.y;
    }

    const float M    = (float)NROWS;
    const float mean = g_stat[f] / M;
    const float var  = g_stat[32 + f] / M - mean * mean;
    const float A    = gamma[f] * rsqrtf(var + 1e-5f);
    const float C    = (beta[f] - mean * A) * wsum;
    g_ya[((size_t)(bt0 +  0) * N_NODES + m) * FEAT + f] = A * a0 + C;
    g_ya[((size_t)(bt0 +  8) * N_NODES + m) * FEAT + f] = A * a1 + C;
    g_ya[((size_t)(bt0 + 16) * N_NODES + m) * FEAT + f] = A * a2 + C;
    g_ya[((size_t)(bt0 + 24) * N_NODES + m) * FEAT + f] = A * a3 + C;
}

// ============================================================
// Kernel 4: GRU scan via mma.sync m16n8k16 fp16 (3-term split).
// block = 64 nodes x 1 batch, 256 threads, 2 blocks/SM, grid 256.
// R10 structure (hprev in regs, ya prefetch during GEMM) +
// per-warp chunk-order rotation + vectorized h-frag writeback.
// ============================================================
#define GK16(C, ACCN)                                                             \
{                                                                                 \
    const uint4 ah0 = *(const uint4*)&sAh[(((C) * 4 + mq * 2    ) * 32 + lane) * 4]; \
    const uint4 al0 = *(const uint4*)&sAl[(((C) * 4 + mq * 2    ) * 32 + lane) * 4]; \
    const uint4 ah1 = *(const uint4*)&sAh[(((C) * 4 + mq * 2 + 1) * 32 + lane) * 4]; \
    const uint4 al1 = *(const uint4*)&sAl[(((C) * 4 + mq * 2 + 1) * 32 + lane) * 4]; \
    _Pragma("unroll")                                                             \
    for (int tt = 0; tt < 6; ++tt) {                                              \
        const uint4 bq = *(const uint4*)&sB[(((C) * 24 + tbase + tt) * 32 + lane) * 4]; \
        const uint2 bh = make_uint2(bq.x, bq.y);                                  \
        const uint2 bl = make_uint2(bq.z, bq.w);                                  \
        float* c0p; float* c1p;                                                   \
        if (tt < 4) { c0p = accRZ[0][tt];     c1p = accRZ[1][tt];     }           \
        else        { c0p = ACCN[0][tt - 4];  c1p = ACCN[1][tt - 4];  }           \
        mma16(c0p, ah0, bh); mma16(c0p, al0, bh); mma16(c0p, ah0, bl);            \
        mma16(c1p, ah1, bh); mma16(c1p, al1, bh); mma16(c1p, ah1, bl);            \
    }                                                                             \
}

__global__ void __launch_bounds__(GT, 2)
gru_mma_kernel(const float* __restrict__ Whh,
               const float* __restrict__ bhh,
               const float* __restrict__ Wd,
               const float* __restrict__ bd,
               float* __restrict__ out)
{
    extern __shared__ float sm[];
    float* sB    = sm + O_B;
    float* sAh   = sm + O_AH;
    float* sAl   = sm + O_AL;
    float* sBias = sm + O_BIAS;
    float* sWd   = sm + O_WD;
    float* sHead = sm + O_HEAD;

    const int tid  = threadIdx.x;
    const int wid  = tid >> 5;
    const int lane = tid & 31;
    const int mq   = wid >> 2;          // m-group 0..1 (m16 tiles mq*2, mq*2+1)
    const int q    = wid & 3;           // col-group 0..3 (hd in [q*16, q*16+16))
    const int tbase = q * 6;

    const int b   = blockIdx.x >> 6;
    const int gm0 = (blockIdx.x & 63) * NP;

    // ---- zero A fragment regions (h0 = 0) ----
    for (int i = tid; i < 3072; i += GT) { sAh[i] = 0.0f; sAl[i] = 0.0f; }

    // ---- stage B fragments (fp16 hi/lo, q-major tile order) ----
    {
        __half* pB = (__half*)sB;
        for (int idx = tid; idx < 96 * G3; idx += GT) {
            const int k = idx / G3, n = idx % G3;
            const float w = (k < 32) ? g_Wcomb[k * G3 + n] : Whh[(k - 32) * G3 + n];
            const __half hh = __float2half_rn(w);
            const __half hl = __float2half_rn(w - __half2float(hh));
            const int g    = n >> 6;
            const int hd   = n & 63;
            const int j    = hd >> 3;
            const int qq   = j >> 1;
            const int sub  = j & 1;
            const int tile = qq * 6 + g * 2 + sub;
            const int ccol = hd & 7;
            const int chunk = k >> 4;
            const int rem   = k & 15;
            const int lt    = ccol * 4 + ((rem & 7) >> 1);
            const int regB  = (rem >= 8) ? 1 : 0;
            const int hb    = rem & 1;
            const int base  = ((chunk * 24 + tile) * 32 + lt) * 4;
            pB[(base + regB) * 2 + hb]     = hh;
            pB[(base + 2 + regB) * 2 + hb] = hl;
        }
    }
    if (tid < HDIM) {
        sBias[tid]       = g_bcomb[tid]       + bhh[tid];        // r
        sBias[64 + tid]  = g_bcomb[64 + tid]  + bhh[64 + tid];   // z
        sBias[128 + tid] = g_bcomb[128 + tid];                   // n_i
        sBias[192 + tid] = bhh[128 + tid];                       // n_h
        sWd[tid]         = Wd[tid];
    }
    const float bdv = bd[0];

    // ---- epilogue geometry ----
    const int gr = lane >> 2;
    const int c0 = (lane & 3) * 2;

    float hprev[2][2][4];
    #pragma unroll
    for (int m = 0; m < 2; ++m)
        #pragma unroll
        for (int sub = 0; sub < 2; ++sub)
            #pragma unroll
            for (int s = 0; s < 4; ++s) hprev[m][sub][s] = 0.0f;

    // ---- ya staging geometry ----
    const int nodeS = tid >> 2;           // 0..63
    const int fc    = tid & 3;            // feature chunk: f base = fc*8
    const int baseS = (((fc >> 1) * 4 + (nodeS >> 4)) * 32 + (nodeS & 7) * 4) * 4
                      + ((fc & 1) ? 2 : 0) + (((nodeS & 15) >= 8) ? 1 : 0);

    // ---- stage ya_0 ----
    {
        const float* p = g_ya + ((size_t)(b * TSTEPS) * N_NODES + gm0 + nodeS) * FEAT + fc * 8;
        const float4 q0 = *(const float4*)(p);
        const float4 q1 = *(const float4*)(p + 4);
        float v[8];
        *(float4*)(v) = q0; *(float4*)(v + 4) = q1;
        #pragma unroll
        for (int j = 0; j < 4; ++j) {
            const float a = v[2 * j], bb = v[2 * j + 1];
            const __half ha = __float2half_rn(a);
            const __half hb = __float2half_rn(bb);
            sAh[baseS + j * 4] = __uint_as_float(pack_f16x2(a, bb));
            sAl[baseS + j * 4] = __uint_as_float(pack_f16x2(a - __half2float(ha),
                                                            bb - __half2float(hb)));
        }
    }
    __syncthreads();

    float4 pf0, pf1;

    for (int t8 = 0; t8 < TSTEPS; ++t8) {
        // ---- accumulators ----
        float accRZ[2][4][4], accNi[2][2][4], accNh[2][2][4];
        #pragma unroll
        for (int m = 0; m < 2; ++m) {
            #pragma unroll
            for (int t = 0; t < 4; ++t)
                #pragma unroll
                for (int s = 0; s < 4; ++s) accRZ[m][t][s] = 0.0f;
            #pragma unroll
            for (int t = 0; t < 2; ++t)
                #pragma unroll
                for (int s = 0; s < 4; ++s) { accNi[m][t][s] = 0.0f; accNh[m][t][s] = 0.0f; }
        }

        // rotated chunk order (per-warp de-convoy); ya chunks -> accNi, h chunks -> accNh
        if (q & 1) { GK16(1, accNi) GK16(0, accNi) }
        else       { GK16(0, accNi) GK16(1, accNi) }
        {
            const int r0 = 2 + ((q + 0) & 3);
            const int r1 = 2 + ((q + 1) & 3);
            const int r2 = 2 + ((q + 2) & 3);
            const int r3 = 2 + ((q + 3) & 3);
            GK16(r0, accNh) GK16(r1, accNh) GK16(r2, accNh) GK16(r3, accNh)
        }

        // prefetch next ya during GEMM
        if (t8 + 1 < TSTEPS) {
            const float* p = g_ya + ((size_t)(b * TSTEPS + t8 + 1) * N_NODES + gm0 + nodeS) * FEAT + fc * 8;
            pf0 = *(const float4*)(p);
            pf1 = *(const float4*)(p + 4);
        }
        __syncthreads();   // all warps done reading A frags (ya_t + h_t)

        // ---- register epilogue ----
        float hp[2][2] = {{0.f, 0.f}, {0.f, 0.f}};
        #pragma unroll
        for (int m = 0; m < 2; ++m) {
            uint4 hhv, hlv;
            #pragma unroll
            for (int sub = 0; sub < 2; ++sub) {
                float hv[4];
                #pragma unroll
                for (int s = 0; s < 4; ++s) {
                    const int hd = q * 16 + sub * 8 + c0 + (s & 1);
                    const float r = sigm(accRZ[m][sub][s]     + sBias[hd]);
                    const float z = sigm(accRZ[m][2 + sub][s] + sBias[64 + hd]);
                    const float n = tanh_fast(accNi[m][sub][s] + sBias[128 + hd]
                                              + r * (accNh[m][sub][s] + sBias[192 + hd]));
                    hv[s] = (1.0f - z) * n + z * hprev[m][sub][s];
                    hprev[m][sub][s] = hv[s];
                    hp[m][s >> 1] += hv[s] * sWd[hd];
                }
                const __half a0 = __float2half_rn(hv[0]);
                const __half a1 = __float2half_rn(hv[1]);
                const __half a2 = __float2half_rn(hv[2]);
                const __half a3 = __float2half_rn(hv[3]);
                const uint32_t wh0 = pack_f16x2(hv[0], hv[1]);
                const uint32_t wh1 = pack_f16x2(hv[2], hv[3]);
                const uint32_t wl0 = pack_f16x2(hv[0] - __half2float(a0), hv[1] - __half2float(a1));
                const uint32_t wl1 = pack_f16x2(hv[2] - __half2float(a2), hv[3] - __half2float(a3));
                if (sub == 0) { hhv.x = wh0; hhv.y = wh1; hlv.x = wl0; hlv.y = wl1; }
                else          { hhv.z = wh0; hhv.w = wh1; hlv.z = wl0; hlv.w = wl1; }
            }
            // vectorized h-frag writeback (16B contiguous per (m, lane))
            const int base = (((2 + q) * 4 + mq * 2 + m) * 32 + lane) * 4;
            *(uint4*)&sAh[base] = hhv;
            *(uint4*)&sAl[base] = hlv;
        }
        // stage ya_{t+1} (chunks 0-1, disjoint from h chunks 2-5)
        if (t8 + 1 < TSTEPS) {
            float v[8];
            *(float4*)(v) = pf0; *(float4*)(v + 4) = pf1;
            #pragma unroll
            for (int j = 0; j < 4; ++j) {
                const float a = v[2 * j], bb = v[2 * j + 1];
                const __half ha = __float2half_rn(a);
                const __half hb = __float2half_rn(bb);
                sAh[baseS + j * 4] = __uint_as_float(pack_f16x2(a, bb));
                sAl[baseS + j * 4] = __uint_as_float(pack_f16x2(a - __half2float(ha),
                                                                bb - __half2float(hb)));
            }
        }
        // head reduce across the 4 lanes sharing gr
        #pragma unroll
        for (int m = 0; m < 2; ++m) {
            hp[m][0] += __shfl_xor_sync(0xffffffffu, hp[m][0], 1);
            hp[m][0] += __shfl_xor_sync(0xffffffffu, hp[m][0], 2);
            hp[m][1] += __shfl_xor_sync(0xffffffffu, hp[m][1], 1);
            hp[m][1] += __shfl_xor_sync(0xffffffffu, hp[m][1], 2);
        }
        if ((lane & 3) == 0) {
            #pragma unroll
            for (int m = 0; m < 2; ++m) {
                const int node = (mq * 2 + m) * 16 + gr;
                sHead[q * 64 + node]     = hp[m][0];
                sHead[q * 64 + node + 8] = hp[m][1];
            }
        }
        __syncthreads();   // h frags + ya frags + sHead complete

        if (tid < NP) {
            out[(size_t)(b * TSTEPS + t8) * N_NODES + gm0 + tid] =
                bdv + sHead[tid] + sHead[64 + tid] + sHead[128 + tid] + sHead[192 + tid];
        }
        // out STG overlaps the next iteration's GEMM (no barrier between).
    }
}

// ============================================================
// launch
// ============================================================
extern "C" void kernel_launch(void* const* d_in, const int* in_sizes, int n_in,
                              void* d_out, int out_size)
{
    const float* x     = (const float*)d_in[0];
    const float* adj   = (const float*)d_in[1];
    const float* gamma = (const float*)d_in[2];
    const float* beta  = (const float*)d_in[3];
    const float* Wgcn  = (const float*)d_in[4];
    const float* bgcn  = (const float*)d_in[5];
    const float* Wih   = (const float*)d_in[6];
    const float* Whh   = (const float*)d_in[7];
    const float* bih   = (const float*)d_in[8];
    const float* bhh   = (const float*)d_in[9];
    const float* Wd    = (const float*)d_in[10];
    const float* bd    = (const float*)d_in[11];
    float* out = (float*)d_out;

    const int smem_bytes = SM_FLOATS * (int)sizeof(float);   // 100608
    cudaFuncSetAttribute(gru_mma_kernel, cudaFuncAttributeMaxDynamicSharedMemorySize, smem_bytes);

    prep_kernel<<<512 + N_NODES, 256>>>(adj, x);
    finalize_kernel<<<89, 256>>>(Wgcn, bgcn, Wih, bih);
    agg_kernel<<<N_NODES, 256>>>(gamma, beta);
    gru_mma_kernel<<<BATCH * (N_NODES / NP), GT, smem_bytes>>>(Whh, bhh, Wd, bd, out);
}

// round 13
// speedup vs baseline: 1.5071x; 1.0521x over previous
#include <cuda_runtime.h>
#include <cuda_fp16.h>
#include <cstdint>

#define N_NODES 4096
#define FEAT    32
#define G3      192
#define HDIM    64
#define BATCH   4
#define TSTEPS  8
#define NBT     (BATCH*TSTEPS)           // 32
#define MAXD    128
#define NROWS   (NBT*N_NODES)            // 131072

// ---- gru mma kernel geometry ----
#define NP      64                        // nodes per block
#define GT      256                       // threads (8 warps = 2 m-groups x 4 col-groups)

// smem float offsets (gru)
#define O_B     0                         // B frags [6 k16][24 tiles][32 lanes][bh0 bh1 bl0 bl1]
#define O_AH    18432                     // A hi frags [6 k16][4 m16][32 lanes][4]
#define O_AL    21504                     // A lo frags
#define O_BIAS  24576                     // [256] r|z|ni|nh
#define O_WD    24832                     // [64]
#define O_HEAD  24896                     // [256] (q*64 + node)
#define SM_FLOATS 25152                   // 100608 bytes

// -------- static device scratch --------
__device__ int      g_row_len[N_NODES];
__device__ float    g_row_wsum[N_NODES];
__device__ int2     g_ell_cv[N_NODES * MAXD];
__device__ float    g_Wcomb[FEAT * G3];
__device__ float    g_bcomb[G3];
__device__ float    g_partN[64 * N_NODES];          // TRANSPOSED: [stat c][node n]
__device__ float    g_stat[64];                     // 0-31 sum, 32-63 sumsq
__device__ uint32_t g_xT2[(size_t)N_NODES * 16 * 32];  // [n][btp][f] half2=(bt, bt+16), 8MB
// ya pre-split into gru fragment words: [bt][node][f2], word = f16x2(f=2*f2, f=2*f2+1)
__device__ uint32_t g_yaH[(size_t)NBT * N_NODES * 16];   // 8MB
__device__ uint32_t g_yaL[(size_t)NBT * N_NODES * 16];   // 8MB

// ============================================================
// helpers
// ============================================================
__device__ __forceinline__ float sigm(float v) { return __fdividef(1.0f, 1.0f + __expf(-v)); }
__device__ __forceinline__ float tanh_fast(float v) {
    const float e = __expf(-2.0f * v);
    return __fdividef(1.0f - e, 1.0f + e);
}
// pack two floats to f16x2 (first arg -> low half)
__device__ __forceinline__ uint32_t pack_f16x2(float lo_val, float hi_val) {
    uint32_t r;
    asm("cvt.rn.f16x2.f32 %0, %1, %2;" : "=r"(r) : "f"(hi_val), "f"(lo_val));
    return r;
}
__device__ __forceinline__ void mma16(float* d, const uint4& a, const uint2& b) {
    asm volatile(
        "mma.sync.aligned.m16n8k16.row.col.f32.f16.f16.f32 "
        "{%0,%1,%2,%3}, {%4,%5,%6,%7}, {%8,%9}, {%0,%1,%2,%3};"
        : "+f"(d[0]), "+f"(d[1]), "+f"(d[2]), "+f"(d[3])
        : "r"(a.x), "r"(a.y), "r"(a.z), "r"(a.w), "r"(b.x), "r"(b.y));
}

// ============================================================
// Kernel 1 (fused prep): blocks [0,512)   -> dense adj -> packed ELL
//                        blocks [512,4608)-> transpose x (fp16x2) + BN partials
// ============================================================
__global__ void __launch_bounds__(256)
prep_kernel(const float* __restrict__ adj, const float* __restrict__ x)
{
    const int tid  = threadIdx.x;
    const int lane = tid & 31;
    const int w    = tid >> 5;

    if (blockIdx.x < 512) {
        // ---------- ELL build: warp = one adjacency row, MLP=8 ----------
        const int warp = blockIdx.x * 8 + w;
        const float* row = adj + (size_t)warp * N_NODES;
        const int base = warp * MAXD;
        int cnt = 0; float wsum = 0.f;
        #pragma unroll 1
        for (int g = 0; g < N_NODES / 256; ++g) {
            float v[8];
            #pragma unroll
            for (int j = 0; j < 8; ++j) v[j] = row[g * 256 + j * 32 + lane];
            #pragma unroll
            for (int j = 0; j < 8; ++j) {
                const int c = g * 256 + j * 32 + lane;
                wsum += v[j];
                const unsigned mask = __ballot_sync(0xffffffffu, v[j] != 0.0f);
                if (v[j] != 0.0f) {
                    const int pos = cnt + __popc(mask & ((1u << lane) - 1u));
                    if (pos < MAXD) g_ell_cv[base + pos] = make_int2(c, __float_as_int(v[j]));
                }
                cnt += __popc(mask);
            }
        }
        #pragma unroll
        for (int o = 16; o > 0; o >>= 1) wsum += __shfl_xor_sync(0xffffffffu, wsum, o);
        if (lane == 0) {
            g_row_len[warp]  = cnt < MAXD ? cnt : MAXD;
            g_row_wsum[warp] = wsum;
        }
    } else {
        // ---------- transpose to fp16x2 + per-node BN partials ----------
        const int n   = blockIdx.x - 512;
        const int bt  = tid >> 3;
        const int f0  = (tid & 7) * 4;

        __shared__ float sh[8][64];
        __shared__ float xbuf[32][32];

        const float4 v = *(const float4*)(x + ((size_t)bt * N_NODES + n) * FEAT + f0);
        *(float4*)&xbuf[bt][f0] = v;

        float s0 = v.x, s1 = v.y, s2 = v.z, s3 = v.w;
        float q0 = v.x * v.x, q1 = v.y * v.y, q2 = v.z * v.z, q3 = v.w * v.w;
        #pragma unroll
        for (int o = 8; o <= 16; o <<= 1) {
            s0 += __shfl_xor_sync(0xffffffffu, s0, o);
            s1 += __shfl_xor_sync(0xffffffffu, s1, o);
            s2 += __shfl_xor_sync(0xffffffffu, s2, o);
            s3 += __shfl_xor_sync(0xffffffffu, s3, o);
            q0 += __shfl_xor_sync(0xffffffffu, q0, o);
            q1 += __shfl_xor_sync(0xffffffffu, q1, o);
            q2 += __shfl_xor_sync(0xffffffffu, q2, o);
            q3 += __shfl_xor_sync(0xffffffffu, q3, o);
        }
        if (lane < 8) {
            sh[w][f0 + 0]      = s0;  sh[w][f0 + 1]      = s1;
            sh[w][f0 + 2]      = s2;  sh[w][f0 + 3]      = s3;
            sh[w][32 + f0 + 0] = q0;  sh[w][32 + f0 + 1] = q1;
            sh[w][32 + f0 + 2] = q2;  sh[w][32 + f0 + 3] = q3;
        }
        __syncthreads();
        if (tid < 64) {
            float a = 0.f;
            #pragma unroll
            for (int i = 0; i < 8; ++i) a += sh[i][tid];
            g_partN[tid * N_NODES + n] = a;     // transposed layout
        }
        if (tid < 128) {
            const int btp = tid >> 3;
            const int fq  = (tid & 7) * 4;
            const float4 a = *(const float4*)&xbuf[btp][fq];
            const float4 b = *(const float4*)&xbuf[btp + 16][fq];
            uint4 wv;
            wv.x = pack_f16x2(a.x, b.x);
            wv.y = pack_f16x2(a.y, b.y);
            wv.z = pack_f16x2(a.z, b.z);
            wv.w = pack_f16x2(a.w, b.w);
            *(uint4*)&g_xT2[((size_t)n * 16 + btp) * 32 + fq] = wv;
        }
    }
}

// ============================================================
// Kernel 2 (parallel finalize): blocks 0-63  -> stat column reduce
//                               blocks 64-87 -> Wcomb, block 88 -> bcomb
// ============================================================
__global__ void __launch_bounds__(256)
finalize_kernel(const float* __restrict__ Wgcn,
                const float* __restrict__ bgcn,
                const float* __restrict__ Wih,
                const float* __restrict__ bih)
{
    const int tid = threadIdx.x;
    const int bid = blockIdx.x;

    if (bid < 64) {
        __shared__ float red[256];
        const float* p = g_partN + bid * N_NODES;
        float a = 0.f;
        #pragma unroll 4
        for (int i = tid; i < N_NODES; i += 256) a += p[i];
        red[tid] = a;
        __syncthreads();
        #pragma unroll
        for (int s = 128; s > 0; s >>= 1) {
            if (tid < s) red[tid] += red[tid + s];
            __syncthreads();
        }
        if (tid == 0) g_stat[bid] = red[0];
    } else if (bid < 88) {
        const int idx = (bid - 64) * 256 + tid;   // < 6144
        const int f = idx / G3, j = idx % G3;
        float acc = 0.f;
        #pragma unroll 8
        for (int c = 0; c < 32; ++c) acc += Wgcn[f * 32 + c] * Wih[c * G3 + j];
        g_Wcomb[idx] = acc;
    } else {
        if (tid < G3) {
            float acc = bih[tid];
            #pragma unroll 8
            for (int c = 0; c < 32; ++c) acc += bgcn[c] * Wih[c * G3 + tid];
            g_bcomb[tid] = acc;
        }
    }
}

// ============================================================
// Kernel 3: aggregation (one block = one node, all 32 bt), fp16 x.
// thread = (feature-pair f2 = tid&15, btp = tid>>4 covering bt, bt+16).
// One 8B load per neighbor; output = pre-split gru fragment words
// (hi/lo fp16 planes), removing all cvt work from the gru t-loop.
// ============================================================
__global__ void __launch_bounds__(256)
agg_kernel(const float* __restrict__ gamma, const float* __restrict__ beta)
{
    const int m   = blockIdx.x;
    const int tid = threadIdx.x;
    const int f2  = tid & 15;            // feature pair: f0 = 2*f2, f1 = 2*f2+1
    const int btp = tid >> 4;            // covers bt = btp and btp+16

    const int len = g_row_len[m];
    const float wsum = g_row_wsum[m];
    const int2* cv = g_ell_cv + m * MAXD;

    // acc[f in pair][bt in (btp, btp+16)]
    float a00 = 0.f, a01 = 0.f, a10 = 0.f, a11 = 0.f;
    const int off = btp * 32 + f2 * 2;

    int k = 0;
    for (; k + 3 < len; k += 4) {
        const int2 e0 = cv[k], e1 = cv[k + 1], e2 = cv[k + 2], e3 = cv[k + 3];
        const float w0 = __int_as_float(e0.y), w1 = __int_as_float(e1.y);
        const float w2 = __int_as_float(e2.y), w3 = __int_as_float(e3.y);
        const uint2 r0 = *(const uint2*)(g_xT2 + (size_t)e0.x * 512 + off);
        const uint2 r1 = *(const uint2*)(g_xT2 + (size_t)e1.x * 512 + off);
        const uint2 r2 = *(const uint2*)(g_xT2 + (size_t)e2.x * 512 + off);
        const uint2 r3 = *(const uint2*)(g_xT2 + (size_t)e3.x * 512 + off);
        {
            const float2 u0 = __half22float2(*(const __half2*)&r0.x);
            const float2 u1 = __half22float2(*(const __half2*)&r0.y);
            a00 += w0 * u0.x; a01 += w0 * u0.y; a10 += w0 * u1.x; a11 += w0 * u1.y;
        }
        {
            const float2 u0 = __half22float2(*(const __half2*)&r1.x);
            const float2 u1 = __half22float2(*(const __half2*)&r1.y);
            a00 += w1 * u0.x; a01 += w1 * u0.y; a10 += w1 * u1.x; a11 += w1 * u1.y;
        }
        {
            const float2 u0 = __half22float2(*(const __half2*)&r2.x);
            const float2 u1 = __half22float2(*(const __half2*)&r2.y);
            a00 += w2 * u0.x; a01 += w2 * u0.y; a10 += w2 * u1.x; a11 += w2 * u1.y;
        }
        {
            const float2 u0 = __half22float2(*(const __half2*)&r3.x);
            const float2 u1 = __half22float2(*(const __half2*)&r3.y);
            a00 += w3 * u0.x; a01 += w3 * u0.y; a10 += w3 * u1.x; a11 += w3 * u1.y;
        }
    }
    for (; k < len; ++k) {
        const int2 e = cv[k];
        const float w = __int_as_float(e.y);
        const uint2 r = *(const uint2*)(g_xT2 + (size_t)e.x * 512 + off);
        const float2 u0 = __half22float2(*(const __half2*)&r.x);
        const float2 u1 = __half22float2(*(const __half2*)&r.y);
        a00 += w * u0.x; a01 += w * u0.y; a10 += w * u1.x; a11 += w * u1.y;
    }

    const float M = (float)NROWS;
    const int f0i = 2 * f2, f1i = 2 * f2 + 1;
    const float mean0 = g_stat[f0i] / M;
    const float var0  = g_stat[32 + f0i] / M - mean0 * mean0;
    const float A0    = gamma[f0i] * rsqrtf(var0 + 1e-5f);
    const float C0    = (beta[f0i] - mean0 * A0) * wsum;
    const float mean1 = g_stat[f1i] / M;
    const float var1  = g_stat[32 + f1i] / M - mean1 * mean1;
    const float A1    = gamma[f1i] * rsqrtf(var1 + 1e-5f);
    const float C1    = (beta[f1i] - mean1 * A1) * wsum;

    // ya values: (f0,bt), (f1,bt), (f0,bt+16), (f1,bt+16)
    const float y00 = A0 * a00 + C0;   // f0, bt=btp
    const float y10 = A1 * a10 + C1;   // f1, bt=btp
    const float y01 = A0 * a01 + C0;   // f0, bt=btp+16
    const float y11 = A1 * a11 + C1;   // f1, bt=btp+16

    // hi/lo fp16 split, packed per-bt as (f0, f1)
    const __half h00 = __float2half_rn(y00), h10 = __float2half_rn(y10);
    const __half h01 = __float2half_rn(y01), h11 = __float2half_rn(y11);
    const size_t o0 = ((size_t)btp * N_NODES + m) * 16 + f2;
    const size_t o1 = ((size_t)(btp + 16) * N_NODES + m) * 16 + f2;
    g_yaH[o0] = pack_f16x2(y00, y10);
    g_yaL[o0] = pack_f16x2(y00 - __half2float(h00), y10 - __half2float(h10));
    g_yaH[o1] = pack_f16x2(y01, y11);
    g_yaL[o1] = pack_f16x2(y01 - __half2float(h01), y11 - __half2float(h11));
}

// ============================================================
// Kernel 4: GRU scan via mma.sync m16n8k16 fp16 (3-term split).
// block = 64 nodes x 1 batch, 256 threads, 2 blocks/SM, grid 256.
// R10 structure; ya staging is now a pure word copy (pre-split in agg).
// ============================================================
#define GK16(C, ACCN)                                                             \
{                                                                                 \
    const uint4 ah0 = *(const uint4*)&sAh[(((C) * 4 + mq * 2    ) * 32 + lane) * 4]; \
    const uint4 al0 = *(const uint4*)&sAl[(((C) * 4 + mq * 2    ) * 32 + lane) * 4]; \
    const uint4 ah1 = *(const uint4*)&sAh[(((C) * 4 + mq * 2 + 1) * 32 + lane) * 4]; \
    const uint4 al1 = *(const uint4*)&sAl[(((C) * 4 + mq * 2 + 1) * 32 + lane) * 4]; \
    _Pragma("unroll")                                                             \
    for (int tt = 0; tt < 6; ++tt) {                                              \
        const uint4 bq = *(const uint4*)&sB[(((C) * 24 + tbase + tt) * 32 + lane) * 4]; \
        const uint2 bh = make_uint2(bq.x, bq.y);                                  \
        const uint2 bl = make_uint2(bq.z, bq.w);                                  \
        float* c0p; float* c1p;                                                   \
        if (tt < 4) { c0p = accRZ[0][tt];     c1p = accRZ[1][tt];     }           \
        else        { c0p = ACCN[0][tt - 4];  c1p = ACCN[1][tt - 4];  }           \
        mma16(c0p, ah0, bh); mma16(c0p, al0, bh); mma16(c0p, ah0, bl);            \
        mma16(c1p, ah1, bh); mma16(c1p, al1, bh); mma16(c1p, ah1, bl);            \
    }                                                                             \
}

__global__ void __launch_bounds__(GT, 2)
gru_mma_kernel(const float* __restrict__ Whh,
               const float* __restrict__ bhh,
               const float* __restrict__ Wd,
               const float* __restrict__ bd,
               float* __restrict__ out)
{
    extern __shared__ float sm[];
    float* sB    = sm + O_B;
    float* sAh   = sm + O_AH;
    float* sAl   = sm + O_AL;
    float* sBias = sm + O_BIAS;
    float* sWd   = sm + O_WD;
    float* sHead = sm + O_HEAD;

    const int tid  = threadIdx.x;
    const int wid  = tid >> 5;
    const int lane = tid & 31;
    const int mq   = wid >> 2;          // m-group 0..1 (m16 tiles mq*2, mq*2+1)
    const int q    = wid & 3;           // col-group 0..3 (hd in [q*16, q*16+16))
    const int tbase = q * 6;

    const int b   = blockIdx.x >> 6;
    const int gm0 = (blockIdx.x & 63) * NP;

    // ---- zero A fragment regions (h0 = 0) ----
    for (int i = tid; i < 3072; i += GT) { sAh[i] = 0.0f; sAl[i] = 0.0f; }

    // ---- stage B fragments (fp16 hi/lo, q-major tile order) ----
    {
        __half* pB = (__half*)sB;
        for (int idx = tid; idx < 96 * G3; idx += GT) {
            const int k = idx / G3, n = idx % G3;
            const float w = (k < 32) ? g_Wcomb[k * G3 + n] : Whh[(k - 32) * G3 + n];
            const __half hh = __float2half_rn(w);
            const __half hl = __float2half_rn(w - __half2float(hh));
            const int g    = n >> 6;
            const int hd   = n & 63;
            const int j    = hd >> 3;
            const int qq   = j >> 1;
            const int sub  = j & 1;
            const int tile = qq * 6 + g * 2 + sub;
            const int ccol = hd & 7;
            const int chunk = k >> 4;
            const int rem   = k & 15;
            const int lt    = ccol * 4 + ((rem & 7) >> 1);
            const int regB  = (rem >= 8) ? 1 : 0;
            const int hb    = rem & 1;
            const int base  = ((chunk * 24 + tile) * 32 + lt) * 4;
            pB[(base + regB) * 2 + hb]     = hh;
            pB[(base + 2 + regB) * 2 + hb] = hl;
        }
    }
    if (tid < HDIM) {
        sBias[tid]       = g_bcomb[tid]       + bhh[tid];        // r
        sBias[64 + tid]  = g_bcomb[64 + tid]  + bhh[64 + tid];   // z
        sBias[128 + tid] = g_bcomb[128 + tid];                   // n_i
        sBias[192 + tid] = bhh[128 + tid];                       // n_h
        sWd[tid]         = Wd[tid];
    }
    const float bdv = bd[0];

    // ---- epilogue geometry ----
    const int gr = lane >> 2;
    const int c0 = (lane & 3) * 2;

    float hprev[2][2][4];
    #pragma unroll
    for (int m = 0; m < 2; ++m)
        #pragma unroll
        for (int sub = 0; sub < 2; ++sub)
            #pragma unroll
            for (int s = 0; s < 4; ++s) hprev[m][sub][s] = 0.0f;

    // ---- ya staging geometry (word copy from pre-split planes) ----
    const int nodeS = tid >> 2;           // 0..63
    const int fc    = tid & 3;            // word group: words fc*4 .. fc*4+3
    const int baseS = (((fc >> 1) * 4 + (nodeS >> 4)) * 32 + (nodeS & 7) * 4) * 4
                      + ((fc & 1) ? 2 : 0) + (((nodeS & 15) >= 8) ? 1 : 0);

    // ---- stage ya_0 ----
    {
        const size_t po = ((size_t)(b * TSTEPS) * N_NODES + gm0 + nodeS) * 16 + fc * 4;
        const uint4 hv = *(const uint4*)(g_yaH + po);
        const uint4 lv = *(const uint4*)(g_yaL + po);
        sAh[baseS + 0]  = __uint_as_float(hv.x);
        sAh[baseS + 4]  = __uint_as_float(hv.y);
        sAh[baseS + 8]  = __uint_as_float(hv.z);
        sAh[baseS + 12] = __uint_as_float(hv.w);
        sAl[baseS + 0]  = __uint_as_float(lv.x);
        sAl[baseS + 4]  = __uint_as_float(lv.y);
        sAl[baseS + 8]  = __uint_as_float(lv.z);
        sAl[baseS + 12] = __uint_as_float(lv.w);
    }
    __syncthreads();

    uint4 pfH, pfL;

    for (int t8 = 0; t8 < TSTEPS; ++t8) {
        // ---- accumulators ----
        float accRZ[2][4][4], accNi[2][2][4], accNh[2][2][4];
        #pragma unroll
        for (int m = 0; m < 2; ++m) {
            #pragma unroll
            for (int t = 0; t < 4; ++t)
                #pragma unroll
                for (int s = 0; s < 4; ++s) accRZ[m][t][s] = 0.0f;
            #pragma unroll
            for (int t = 0; t < 2; ++t)
                #pragma unroll
                for (int s = 0; s < 4; ++s) { accNi[m][t][s] = 0.0f; accNh[m][t][s] = 0.0f; }
        }

        GK16(0, accNi) GK16(1, accNi)
        GK16(2, accNh) GK16(3, accNh) GK16(4, accNh) GK16(5, accNh)

        // prefetch next ya during GEMM
        if (t8 + 1 < TSTEPS) {
            const size_t po = ((size_t)(b * TSTEPS + t8 + 1) * N_NODES + gm0 + nodeS) * 16 + fc * 4;
            pfH = *(const uint4*)(g_yaH + po);
            pfL = *(const uint4*)(g_yaL + po);
        }
        __syncthreads();   // all warps done reading A frags (ya_t + h_t)

        // ---- register epilogue ----
        float hp[2][2] = {{0.f, 0.f}, {0.f, 0.f}};
        #pragma unroll
        for (int m = 0; m < 2; ++m) {
            #pragma unroll
            for (int sub = 0; sub < 2; ++sub) {
                float hv[4];
                #pragma unroll
                for (int s = 0; s < 4; ++s) {
                    const int hd = q * 16 + sub * 8 + c0 + (s & 1);
                    const float r = sigm(accRZ[m][sub][s]     + sBias[hd]);
                    const float z = sigm(accRZ[m][2 + sub][s] + sBias[64 + hd]);
                    const float n = tanh_fast(accNi[m][sub][s] + sBias[128 + hd]
                                              + r * (accNh[m][sub][s] + sBias[192 + hd]));
                    hv[s] = (1.0f - z) * n + z * hprev[m][sub][s];
                    hprev[m][sub][s] = hv[s];
                    hp[m][s >> 1] += hv[s] * sWd[hd];
                }
                // write h back into A fragments at k = 32 + q*16 + sub*8 + cc
                const int base = (((2 + q) * 4 + mq * 2 + m) * 32 + lane) * 4;
                const __half a0 = __float2half_rn(hv[0]);
                const __half a1 = __float2half_rn(hv[1]);
                const __half a2 = __float2half_rn(hv[2]);
                const __half a3 = __float2half_rn(hv[3]);
                sAh[base + sub * 2]     = __uint_as_float(pack_f16x2(hv[0], hv[1]));
                sAh[base + sub * 2 + 1] = __uint_as_float(pack_f16x2(hv[2], hv[3]));
                sAl[base + sub * 2]     = __uint_as_float(pack_f16x2(hv[0] - __half2float(a0),
                                                                     hv[1] - __half2float(a1)));
                sAl[base + sub * 2 + 1] = __uint_as_float(pack_f16x2(hv[2] - __half2float(a2),
                                                                     hv[3] - __half2float(a3)));
            }
        }
        // stage ya_{t+1} (chunks 0-1, disjoint from h chunks 2-5): pure word copy
        if (t8 + 1 < TSTEPS) {
            sAh[baseS + 0]  = __uint_as_float(pfH.x);
            sAh[baseS + 4]  = __uint_as_float(pfH.y);
            sAh[baseS + 8]  = __uint_as_float(pfH.z);
            sAh[baseS + 12] = __uint_as_float(pfH.w);
            sAl[baseS + 0]  = __uint_as_float(pfL.x);
            sAl[baseS + 4]  = __uint_as_float(pfL.y);
            sAl[baseS + 8]  = __uint_as_float(pfL.z);
            sAl[baseS + 12] = __uint_as_float(pfL.w);
        }
        // head reduce across the 4 lanes sharing gr
        #pragma unroll
        for (int m = 0; m < 2; ++m) {
            hp[m][0] += __shfl_xor_sync(0xffffffffu, hp[m][0], 1);
            hp[m][0] += __shfl_xor_sync(0xffffffffu, hp[m][0], 2);
            hp[m][1] += __shfl_xor_sync(0xffffffffu, hp[m][1], 1);
            hp[m][1] += __shfl_xor_sync(0xffffffffu, hp[m][1], 2);
        }
        if ((lane & 3) == 0) {
            #pragma unroll
            for (int m = 0; m < 2; ++m) {
                const int node = (mq * 2 + m) * 16 + gr;
                sHead[q * 64 + node]     = hp[m][0];
                sHead[q * 64 + node + 8] = hp[m][1];
            }
        }
        __syncthreads();   // h frags + ya frags + sHead complete

        if (tid < NP) {
            out[(size_t)(b * TSTEPS + t8) * N_NODES + gm0 + tid] =
                bdv + sHead[tid] + sHead[64 + tid] + sHead[128 + tid] + sHead[192 + tid];
        }
        // out STG overlaps the next iteration's GEMM (no barrier between).
    }
}

// ============================================================
// launch
// ============================================================
extern "C" void kernel_launch(void* const* d_in, const int* in_sizes, int n_in,
                              void* d_out, int out_size)
{
    const float* x     = (const float*)d_in[0];
    const float* adj   = (const float*)d_in[1];
    const float* gamma = (const float*)d_in[2];
    const float* beta  = (const float*)d_in[3];
    const float* Wgcn  = (const float*)d_in[4];
    const float* bgcn  = (const float*)d_in[5];
    const float* Wih   = (const float*)d_in[6];
    const float* Whh   = (const float*)d_in[7];
    const float* bih   = (const float*)d_in[8];
    const float* bhh   = (const float*)d_in[9];
    const float* Wd    = (const float*)d_in[10];
    const float* bd    = (const float*)d_in[11];
    float* out = (float*)d_out;

    const int smem_bytes = SM_FLOATS * (int)sizeof(float);   // 100608
    cudaFuncSetAttribute(gru_mma_kernel, cudaFuncAttributeMaxDynamicSharedMemorySize, smem_bytes);

    prep_kernel<<<512 + N_NODES, 256>>>(adj, x);
    finalize_kernel<<<89, 256>>>(Wgcn, bgcn, Wih, bih);
    agg_kernel<<<N_NODES, 256>>>(gamma, beta);
    gru_mma_kernel<<<BATCH * (N_NODES / NP), GT, smem_bytes>>>(Whh, bhh, Wd, bd, out);
}

// round 14
// speedup vs baseline: 1.7882x; 1.1865x over previous
#include <cuda_runtime.h>
#include <cuda_fp16.h>
#include <cstdint>

#define N_NODES 4096
#define FEAT    32
#define G3      192
#define HDIM    64
#define BATCH   4
#define TSTEPS  8
#define NBT     (BATCH*TSTEPS)           // 32
#define MAXD    128
#define NROWS   (NBT*N_NODES)            // 131072

// ---- gru mma kernel geometry ----
#define NP      64                        // nodes per block
#define GT      256                       // threads (8 warps = 2 m-groups x 4 col-groups)

// smem float offsets (gru) -- B is fp16-hi only now
#define O_B     0                         // B frags [6 k16][24 tiles][32 lanes][2 words]
#define O_AH    9216                      // A hi frags [6 k16][4 m16][32 lanes][4]
#define O_AL    12288                     // A lo frags
#define O_BIAS  15360                     // [256] r|z|ni|nh
#define O_WD    15616                     // [64]
#define O_HEAD  15680                     // [256] (q*64 + node)
#define SM_FLOATS 15936                   // 63744 bytes

// -------- static device scratch --------
__device__ int      g_row_len[N_NODES];
__device__ float    g_row_wsum[N_NODES];
__device__ int2     g_ell_cv[N_NODES * MAXD];
__device__ float    g_Wcomb[FEAT * G3];
__device__ float    g_bcomb[G3];
__device__ float    g_partN[64 * N_NODES];          // TRANSPOSED: [stat c][node n]
__device__ float    g_stat[64];                     // 0-31 sum, 32-63 sumsq
__device__ uint32_t g_xT2[(size_t)N_NODES * 16 * 32];  // [n][btp][f] half2=(bt, bt+16), 8MB
// ya pre-split into gru fragment words: [bt][node][f2], word = f16x2(f=2*f2, f=2*f2+1)
__device__ uint32_t g_yaH[(size_t)NBT * N_NODES * 16];   // 8MB
__device__ uint32_t g_yaL[(size_t)NBT * N_NODES * 16];   // 8MB

// ============================================================
// helpers
// ============================================================
__device__ __forceinline__ float sigm(float v) { return __fdividef(1.0f, 1.0f + __expf(-v)); }
__device__ __forceinline__ float tanh_fast(float v) {
    const float e = __expf(-2.0f * v);
    return __fdividef(1.0f - e, 1.0f + e);
}
// pack two floats to f16x2 (first arg -> low half)
__device__ __forceinline__ uint32_t pack_f16x2(float lo_val, float hi_val) {
    uint32_t r;
    asm("cvt.rn.f16x2.f32 %0, %1, %2;" : "=r"(r) : "f"(hi_val), "f"(lo_val));
    return r;
}
__device__ __forceinline__ void mma16(float* d, const uint4& a, const uint2& b) {
    asm volatile(
        "mma.sync.aligned.m16n8k16.row.col.f32.f16.f16.f32 "
        "{%0,%1,%2,%3}, {%4,%5,%6,%7}, {%8,%9}, {%0,%1,%2,%3};"
        : "+f"(d[0]), "+f"(d[1]), "+f"(d[2]), "+f"(d[3])
        : "r"(a.x), "r"(a.y), "r"(a.z), "r"(a.w), "r"(b.x), "r"(b.y));
}

// ============================================================
// Kernel 1 (fused prep): blocks [0,512)   -> dense adj -> packed ELL
//                        blocks [512,4608)-> transpose x (fp16x2) + BN partials
// ============================================================
__global__ void __launch_bounds__(256)
prep_kernel(const float* __restrict__ adj, const float* __restrict__ x)
{
    const int tid  = threadIdx.x;
    const int lane = tid & 31;
    const int w    = tid >> 5;

    if (blockIdx.x < 512) {
        // ---------- ELL build: warp = one adjacency row, MLP=8 ----------
        const int warp = blockIdx.x * 8 + w;
        const float* row = adj + (size_t)warp * N_NODES;
        const int base = warp * MAXD;
        int cnt = 0; float wsum = 0.f;
        #pragma unroll 1
        for (int g = 0; g < N_NODES / 256; ++g) {
            float v[8];
            #pragma unroll
            for (int j = 0; j < 8; ++j) v[j] = row[g * 256 + j * 32 + lane];
            #pragma unroll
            for (int j = 0; j < 8; ++j) {
                const int c = g * 256 + j * 32 + lane;
                wsum += v[j];
                const unsigned mask = __ballot_sync(0xffffffffu, v[j] != 0.0f);
                if (v[j] != 0.0f) {
                    const int pos = cnt + __popc(mask & ((1u << lane) - 1u));
                    if (pos < MAXD) g_ell_cv[base + pos] = make_int2(c, __float_as_int(v[j]));
                }
                cnt += __popc(mask);
            }
        }
        #pragma unroll
        for (int o = 16; o > 0; o >>= 1) wsum += __shfl_xor_sync(0xffffffffu, wsum, o);
        if (lane == 0) {
            g_row_len[warp]  = cnt < MAXD ? cnt : MAXD;
            g_row_wsum[warp] = wsum;
        }
    } else {
        // ---------- transpose to fp16x2 + per-node BN partials ----------
        const int n   = blockIdx.x - 512;
        const int bt  = tid >> 3;
        const int f0  = (tid & 7) * 4;

        __shared__ float sh[8][64];
        __shared__ float xbuf[32][32];

        const float4 v = *(const float4*)(x + ((size_t)bt * N_NODES + n) * FEAT + f0);
        *(float4*)&xbuf[bt][f0] = v;

        float s0 = v.x, s1 = v.y, s2 = v.z, s3 = v.w;
        float q0 = v.x * v.x, q1 = v.y * v.y, q2 = v.z * v.z, q3 = v.w * v.w;
        #pragma unroll
        for (int o = 8; o <= 16; o <<= 1) {
            s0 += __shfl_xor_sync(0xffffffffu, s0, o);
            s1 += __shfl_xor_sync(0xffffffffu, s1, o);
            s2 += __shfl_xor_sync(0xffffffffu, s2, o);
            s3 += __shfl_xor_sync(0xffffffffu, s3, o);
            q0 += __shfl_xor_sync(0xffffffffu, q0, o);
            q1 += __shfl_xor_sync(0xffffffffu, q1, o);
            q2 += __shfl_xor_sync(0xffffffffu, q2, o);
            q3 += __shfl_xor_sync(0xffffffffu, q3, o);
        }
        if (lane < 8) {
            sh[w][f0 + 0]      = s0;  sh[w][f0 + 1]      = s1;
            sh[w][f0 + 2]      = s2;  sh[w][f0 + 3]      = s3;
            sh[w][32 + f0 + 0] = q0;  sh[w][32 + f0 + 1] = q1;
            sh[w][32 + f0 + 2] = q2;  sh[w][32 + f0 + 3] = q3;
        }
        __syncthreads();
        if (tid < 64) {
            float a = 0.f;
            #pragma unroll
            for (int i = 0; i < 8; ++i) a += sh[i][tid];
            g_partN[tid * N_NODES + n] = a;     // transposed layout
        }
        if (tid < 128) {
            const int btp = tid >> 3;
            const int fq  = (tid & 7) * 4;
            const float4 a = *(const float4*)&xbuf[btp][fq];
            const float4 b = *(const float4*)&xbuf[btp + 16][fq];
            uint4 wv;
            wv.x = pack_f16x2(a.x, b.x);
            wv.y = pack_f16x2(a.y, b.y);
            wv.z = pack_f16x2(a.z, b.z);
            wv.w = pack_f16x2(a.w, b.w);
            *(uint4*)&g_xT2[((size_t)n * 16 + btp) * 32 + fq] = wv;
        }
    }
}

// ============================================================
// Kernel 2 (parallel finalize): blocks 0-63  -> stat column reduce
//                               blocks 64-87 -> Wcomb, block 88 -> bcomb
// ============================================================
__global__ void __launch_bounds__(256)
finalize_kernel(const float* __restrict__ Wgcn,
                const float* __restrict__ bgcn,
                const float* __restrict__ Wih,
                const float* __restrict__ bih)
{
    const int tid = threadIdx.x;
    const int bid = blockIdx.x;

    if (bid < 64) {
        __shared__ float red[256];
        const float* p = g_partN + bid * N_NODES;
        float a = 0.f;
        #pragma unroll 4
        for (int i = tid; i < N_NODES; i += 256) a += p[i];
        red[tid] = a;
        __syncthreads();
        #pragma unroll
        for (int s = 128; s > 0; s >>= 1) {
            if (tid < s) red[tid] += red[tid + s];
            __syncthreads();
        }
        if (tid == 0) g_stat[bid] = red[0];
    } else if (bid < 88) {
        const int idx = (bid - 64) * 256 + tid;   // < 6144
        const int f = idx / G3, j = idx % G3;
        float acc = 0.f;
        #pragma unroll 8
        for (int c = 0; c < 32; ++c) acc += Wgcn[f * 32 + c] * Wih[c * G3 + j];
        g_Wcomb[idx] = acc;
    } else {
        if (tid < G3) {
            float acc = bih[tid];
            #pragma unroll 8
            for (int c = 0; c < 32; ++c) acc += bgcn[c] * Wih[c * G3 + tid];
            g_bcomb[tid] = acc;
        }
    }
}

// ============================================================
// Kernel 3: aggregation (one block = one node, all 32 bt), fp16 x.
// thread = (feature-pair f2 = tid&15, btp = tid>>4 covering bt, bt+16).
// Output = pre-split gru fragment words (hi/lo fp16 planes).
// ============================================================
__global__ void __launch_bounds__(256)
agg_kernel(const float* __restrict__ gamma, const float* __restrict__ beta)
{
    const int m   = blockIdx.x;
    const int tid = threadIdx.x;
    const int f2  = tid & 15;            // feature pair: f0 = 2*f2, f1 = 2*f2+1
    const int btp = tid >> 4;            // covers bt = btp and btp+16

    const int len = g_row_len[m];
    const float wsum = g_row_wsum[m];
    const int2* cv = g_ell_cv + m * MAXD;

    float a00 = 0.f, a01 = 0.f, a10 = 0.f, a11 = 0.f;
    const int off = btp * 32 + f2 * 2;

    int k = 0;
    for (; k + 3 < len; k += 4) {
        const int2 e0 = cv[k], e1 = cv[k + 1], e2 = cv[k + 2], e3 = cv[k + 3];
        const float w0 = __int_as_float(e0.y), w1 = __int_as_float(e1.y);
        const float w2 = __int_as_float(e2.y), w3 = __int_as_float(e3.y);
        const uint2 r0 = *(const uint2*)(g_xT2 + (size_t)e0.x * 512 + off);
        const uint2 r1 = *(const uint2*)(g_xT2 + (size_t)e1.x * 512 + off);
        const uint2 r2 = *(const uint2*)(g_xT2 + (size_t)e2.x * 512 + off);
        const uint2 r3 = *(const uint2*)(g_xT2 + (size_t)e3.x * 512 + off);
        {
            const float2 u0 = __half22float2(*(const __half2*)&r0.x);
            const float2 u1 = __half22float2(*(const __half2*)&r0.y);
            a00 += w0 * u0.x; a01 += w0 * u0.y; a10 += w0 * u1.x; a11 += w0 * u1.y;
        }
        {
            const float2 u0 = __half22float2(*(const __half2*)&r1.x);
            const float2 u1 = __half22float2(*(const __half2*)&r1.y);
            a00 += w1 * u0.x; a01 += w1 * u0.y; a10 += w1 * u1.x; a11 += w1 * u1.y;
        }
        {
            const float2 u0 = __half22float2(*(const __half2*)&r2.x);
            const float2 u1 = __half22float2(*(const __half2*)&r2.y);
            a00 += w2 * u0.x; a01 += w2 * u0.y; a10 += w2 * u1.x; a11 += w2 * u1.y;
        }
        {
            const float2 u0 = __half22float2(*(const __half2*)&r3.x);
            const float2 u1 = __half22float2(*(const __half2*)&r3.y);
            a00 += w3 * u0.x; a01 += w3 * u0.y; a10 += w3 * u1.x; a11 += w3 * u1.y;
        }
    }
    for (; k < len; ++k) {
        const int2 e = cv[k];
        const float w = __int_as_float(e.y);
        const uint2 r = *(const uint2*)(g_xT2 + (size_t)e.x * 512 + off);
        const float2 u0 = __half22float2(*(const __half2*)&r.x);
        const float2 u1 = __half22float2(*(const __half2*)&r.y);
        a00 += w * u0.x; a01 += w * u0.y; a10 += w * u1.x; a11 += w * u1.y;
    }

    const float M = (float)NROWS;
    const int f0i = 2 * f2, f1i = 2 * f2 + 1;
    const float mean0 = g_stat[f0i] / M;
    const float var0  = g_stat[32 + f0i] / M - mean0 * mean0;
    const float A0    = gamma[f0i] * rsqrtf(var0 + 1e-5f);
    const float C0    = (beta[f0i] - mean0 * A0) * wsum;
    const float mean1 = g_stat[f1i] / M;
    const float var1  = g_stat[32 + f1i] / M - mean1 * mean1;
    const float A1    = gamma[f1i] * rsqrtf(var1 + 1e-5f);
    const float C1    = (beta[f1i] - mean1 * A1) * wsum;

    const float y00 = A0 * a00 + C0;   // f0, bt=btp
    const float y10 = A1 * a10 + C1;   // f1, bt=btp
    const float y01 = A0 * a01 + C0;   // f0, bt=btp+16
    const float y11 = A1 * a11 + C1;   // f1, bt=btp+16

    const __half h00 = __float2half_rn(y00), h10 = __float2half_rn(y10);
    const __half h01 = __float2half_rn(y01), h11 = __float2half_rn(y11);
    const size_t o0 = ((size_t)btp * N_NODES + m) * 16 + f2;
    const size_t o1 = ((size_t)(btp + 16) * N_NODES + m) * 16 + f2;
    g_yaH[o0] = pack_f16x2(y00, y10);
    g_yaL[o0] = pack_f16x2(y00 - __half2float(h00), y10 - __half2float(h10));
    g_yaH[o1] = pack_f16x2(y01, y11);
    g_yaL[o1] = pack_f16x2(y01 - __half2float(h01), y11 - __half2float(h11));
}

// ============================================================
// Kernel 4: GRU scan via mma.sync m16n8k16 fp16, 2-term split:
//   acc = A_hi @ B16 + A_lo @ B16  (= near-exact A x fp16 weights)
// block = 64 nodes x 1 batch, 256 threads, 2 blocks/SM, grid 256.
// 144 mma/warp/t (was 216); B smem halved (hi plane only).
// ============================================================
#define GK16(C, ACCN)                                                             \
{                                                                                 \
    const uint4 ah0 = *(const uint4*)&sAh[(((C) * 4 + mq * 2    ) * 32 + lane) * 4]; \
    const uint4 al0 = *(const uint4*)&sAl[(((C) * 4 + mq * 2    ) * 32 + lane) * 4]; \
    const uint4 ah1 = *(const uint4*)&sAh[(((C) * 4 + mq * 2 + 1) * 32 + lane) * 4]; \
    const uint4 al1 = *(const uint4*)&sAl[(((C) * 4 + mq * 2 + 1) * 32 + lane) * 4]; \
    _Pragma("unroll")                                                             \
    for (int tt = 0; tt < 6; ++tt) {                                              \
        const uint2 bh = *(const uint2*)&sB[(((C) * 24 + tbase + tt) * 32 + lane) * 2]; \
        float* c0p; float* c1p;                                                   \
        if (tt < 4) { c0p = accRZ[0][tt];     c1p = accRZ[1][tt];     }           \
        else        { c0p = ACCN[0][tt - 4];  c1p = ACCN[1][tt - 4];  }           \
        mma16(c0p, ah0, bh); mma16(c0p, al0, bh);                                 \
        mma16(c1p, ah1, bh); mma16(c1p, al1, bh);                                 \
    }                                                                             \
}

__global__ void __launch_bounds__(GT, 2)
gru_mma_kernel(const float* __restrict__ Whh,
               const float* __restrict__ bhh,
               const float* __restrict__ Wd,
               const float* __restrict__ bd,
               float* __restrict__ out)
{
    extern __shared__ float sm[];
    float* sB    = sm + O_B;
    float* sAh   = sm + O_AH;
    float* sAl   = sm + O_AL;
    float* sBias = sm + O_BIAS;
    float* sWd   = sm + O_WD;
    float* sHead = sm + O_HEAD;

    const int tid  = threadIdx.x;
    const int wid  = tid >> 5;
    const int lane = tid & 31;
    const int mq   = wid >> 2;          // m-group 0..1 (m16 tiles mq*2, mq*2+1)
    const int q    = wid & 3;           // col-group 0..3 (hd in [q*16, q*16+16))
    const int tbase = q * 6;

    const int b   = blockIdx.x >> 6;
    const int gm0 = (blockIdx.x & 63) * NP;

    // ---- zero A fragment regions (h0 = 0) ----
    for (int i = tid; i < 3072; i += GT) { sAh[i] = 0.0f; sAl[i] = 0.0f; }

    // ---- stage B fragments (fp16 hi only, q-major tile order) ----
    {
        __half* pB = (__half*)sB;
        for (int idx = tid; idx < 96 * G3; idx += GT) {
            const int k = idx / G3, n = idx % G3;
            const float w = (k < 32) ? g_Wcomb[k * G3 + n] : Whh[(k - 32) * G3 + n];
            const __half hh = __float2half_rn(w);
            const int g    = n >> 6;
            const int hd   = n & 63;
            const int j    = hd >> 3;
            const int qq   = j >> 1;
            const int sub  = j & 1;
            const int tile = qq * 6 + g * 2 + sub;
            const int ccol = hd & 7;
            const int chunk = k >> 4;
            const int rem   = k & 15;
            const int lt    = ccol * 4 + ((rem & 7) >> 1);
            const int regB  = (rem >= 8) ? 1 : 0;
            const int hb    = rem & 1;
            const int base  = ((chunk * 24 + tile) * 32 + lt) * 2;
            pB[(base + regB) * 2 + hb] = hh;
        }
    }
    if (tid < HDIM) {
        sBias[tid]       = g_bcomb[tid]       + bhh[tid];        // r
        sBias[64 + tid]  = g_bcomb[64 + tid]  + bhh[64 + tid];   // z
        sBias[128 + tid] = g_bcomb[128 + tid];                   // n_i
        sBias[192 + tid] = bhh[128 + tid];                       // n_h
        sWd[tid]         = Wd[tid];
    }
    const float bdv = bd[0];

    // ---- epilogue geometry ----
    const int gr = lane >> 2;
    const int c0 = (lane & 3) * 2;

    float hprev[2][2][4];
    #pragma unroll
    for (int m = 0; m < 2; ++m)
        #pragma unroll
        for (int sub = 0; sub < 2; ++sub)
            #pragma unroll
            for (int s = 0; s < 4; ++s) hprev[m][sub][s] = 0.0f;

    // ---- ya staging geometry (word copy from pre-split planes) ----
    const int nodeS = tid >> 2;           // 0..63
    const int fc    = tid & 3;            // word group: words fc*4 .. fc*4+3
    const int baseS = (((fc >> 1) * 4 + (nodeS >> 4)) * 32 + (nodeS & 7) * 4) * 4
                      + ((fc & 1) ? 2 : 0) + (((nodeS & 15) >= 8) ? 1 : 0);

    // ---- stage ya_0 ----
    {
        const size_t po = ((size_t)(b * TSTEPS) * N_NODES + gm0 + nodeS) * 16 + fc * 4;
        const uint4 hv = *(const uint4*)(g_yaH + po);
        const uint4 lv = *(const uint4*)(g_yaL + po);
        sAh[baseS + 0]  = __uint_as_float(hv.x);
        sAh[baseS + 4]  = __uint_as_float(hv.y);
        sAh[baseS + 8]  = __uint_as_float(hv.z);
        sAh[baseS + 12] = __uint_as_float(hv.w);
        sAl[baseS + 0]  = __uint_as_float(lv.x);
        sAl[baseS + 4]  = __uint_as_float(lv.y);
        sAl[baseS + 8]  = __uint_as_float(lv.z);
        sAl[baseS + 12] = __uint_as_float(lv.w);
    }
    __syncthreads();

    uint4 pfH, pfL;

    for (int t8 = 0; t8 < TSTEPS; ++t8) {
        // ---- accumulators ----
        float accRZ[2][4][4], accNi[2][2][4], accNh[2][2][4];
        #pragma unroll
        for (int m = 0; m < 2; ++m) {
            #pragma unroll
            for (int t = 0; t < 4; ++t)
                #pragma unroll
                for (int s = 0; s < 4; ++s) accRZ[m][t][s] = 0.0f;
            #pragma unroll
            for (int t = 0; t < 2; ++t)
                #pragma unroll
                for (int s = 0; s < 4; ++s) { accNi[m][t][s] = 0.0f; accNh[m][t][s] = 0.0f; }
        }

        GK16(0, accNi) GK16(1, accNi)
        GK16(2, accNh) GK16(3, accNh) GK16(4, accNh) GK16(5, accNh)

        // prefetch next ya during GEMM
        if (t8 + 1 < TSTEPS) {
            const size_t po = ((size_t)(b * TSTEPS + t8 + 1) * N_NODES + gm0 + nodeS) * 16 + fc * 4;
            pfH = *(const uint4*)(g_yaH + po);
            pfL = *(const uint4*)(g_yaL + po);
        }
        __syncthreads();   // all warps done reading A frags (ya_t + h_t)

        // ---- register epilogue ----
        float hp[2][2] = {{0.f, 0.f}, {0.f, 0.f}};
        #pragma unroll
        for (int m = 0; m < 2; ++m) {
            #pragma unroll
            for (int sub = 0; sub < 2; ++sub) {
                float hv[4];
                #pragma unroll
                for (int s = 0; s < 4; ++s) {
                    const int hd = q * 16 + sub * 8 + c0 + (s & 1);
                    const float r = sigm(accRZ[m][sub][s]     + sBias[hd]);
                    const float z = sigm(accRZ[m][2 + sub][s] + sBias[64 + hd]);
                    const float n = tanh_fast(accNi[m][sub][s] + sBias[128 + hd]
                                              + r * (accNh[m][sub][s] + sBias[192 + hd]));
                    hv[s] = (1.0f - z) * n + z * hprev[m][sub][s];
                    hprev[m][sub][s] = hv[s];
                    hp[m][s >> 1] += hv[s] * sWd[hd];
                }
                // write h back into A fragments at k = 32 + q*16 + sub*8 + cc
                const int base = (((2 + q) * 4 + mq * 2 + m) * 32 + lane) * 4;
                const __half a0 = __float2half_rn(hv[0]);
                const __half a1 = __float2half_rn(hv[1]);
                const __half a2 = __float2half_rn(hv[2]);
                const __half a3 = __float2half_rn(hv[3]);
                sAh[base + sub * 2]     = __uint_as_float(pack_f16x2(hv[0], hv[1]));
                sAh[base + sub * 2 + 1] = __uint_as_float(pack_f16x2(hv[2], hv[3]));
                sAl[base + sub * 2]     = __uint_as_float(pack_f16x2(hv[0] - __half2float(a0),
                                                                     hv[1] - __half2float(a1)));
                sAl[base + sub * 2 + 1] = __uint_as_float(pack_f16x2(hv[2] - __half2float(a2),
                                                                     hv[3] - __half2float(a3)));
            }
        }
        // stage ya_{t+1} (chunks 0-1, disjoint from h chunks 2-5): pure word copy
        if (t8 + 1 < TSTEPS) {
            sAh[baseS + 0]  = __uint_as_float(pfH.x);
            sAh[baseS + 4]  = __uint_as_float(pfH.y);
            sAh[baseS + 8]  = __uint_as_float(pfH.z);
            sAh[baseS + 12] = __uint_as_float(pfH.w);
            sAl[baseS + 0]  = __uint_as_float(pfL.x);
            sAl[baseS + 4]  = __uint_as_float(pfL.y);
            sAl[baseS + 8]  = __uint_as_float(pfL.z);
            sAl[baseS + 12] = __uint_as_float(pfL.w);
        }
        // head reduce across the 4 lanes sharing gr
        #pragma unroll
        for (int m = 0; m < 2; ++m) {
            hp[m][0] += __shfl_xor_sync(0xffffffffu, hp[m][0], 1);
            hp[m][0] += __shfl_xor_sync(0xffffffffu, hp[m][0], 2);
            hp[m][1] += __shfl_xor_sync(0xffffffffu, hp[m][1], 1);
            hp[m][1] += __shfl_xor_sync(0xffffffffu, hp[m][1], 2);
        }
        if ((lane & 3) == 0) {
            #pragma unroll
            for (int m = 0; m < 2; ++m) {
                const int node = (mq * 2 + m) * 16 + gr;
                sHead[q * 64 + node]     = hp[m][0];
                sHead[q * 64 + node + 8] = hp[m][1];
            }
        }
        __syncthreads();   // h frags + ya frags + sHead complete

        if (tid < NP) {
            out[(size_t)(b * TSTEPS + t8) * N_NODES + gm0 + tid] =
                bdv + sHead[tid] + sHead[64 + tid] + sHead[128 + tid] + sHead[192 + tid];
        }
        // out STG overlaps the next iteration's GEMM (no barrier between).
    }
}

// ============================================================
// launch
// ============================================================
extern "C" void kernel_launch(void* const* d_in, const int* in_sizes, int n_in,
                              void* d_out, int out_size)
{
    const float* x     = (const float*)d_in[0];
    const float* adj   = (const float*)d_in[1];
    const float* gamma = (const float*)d_in[2];
    const float* beta  = (const float*)d_in[3];
    const float* Wgcn  = (const float*)d_in[4];
    const float* bgcn  = (const float*)d_in[5];
    const float* Wih   = (const float*)d_in[6];
    const float* Whh   = (const float*)d_in[7];
    const float* bih   = (const float*)d_in[8];
    const float* bhh   = (const float*)d_in[9];
    const float* Wd    = (const float*)d_in[10];
    const float* bd    = (const float*)d_in[11];
    float* out = (float*)d_out;

    const int smem_bytes = SM_FLOATS * (int)sizeof(float);   // 63744
    cudaFuncSetAttribute(gru_mma_kernel, cudaFuncAttributeMaxDynamicSharedMemorySize, smem_bytes);

    prep_kernel<<<512 + N_NODES, 256>>>(adj, x);
    finalize_kernel<<<89, 256>>>(Wgcn, bgcn, Wih, bih);
    agg_kernel<<<N_NODES, 256>>>(gamma, beta);
    gru_mma_kernel<<<BATCH * (N_NODES / NP), GT, smem_bytes>>>(Whh, bhh, Wd, bd, out);
}

// round 15
// speedup vs baseline: 2.0073x; 1.1225x over previous
#include <cuda_runtime.h>
#include <cuda_fp16.h>
#include <cstdint>

#define N_NODES 4096
#define FEAT    32
#define G3      192
#define HDIM    64
#define BATCH   4
#define TSTEPS  8
#define NBT     (BATCH*TSTEPS)           // 32
#define MAXD    128
#define NROWS   (NBT*N_NODES)            // 131072

// ---- gru mma kernel geometry ----
#define NP      64                        // nodes per block
#define GT      256                       // threads (8 warps = 2 m-groups x 4 col-groups)

// smem float offsets (gru) -- fp16 everywhere, single plane
#define O_B     0                         // B frags [6 k16][24 tiles][32 lanes][2 words]
#define O_AH    9216                      // A frags [6 k16][4 m16][32 lanes][4 words]
#define O_BIAS  12288                     // [256] r|z|ni|nh
#define O_WD    12544                     // [64]
#define O_HEAD  12608                     // [256] (q*64 + node)
#define SM_FLOATS 12864                   // 51456 bytes

// -------- static device scratch --------
__device__ int      g_row_len[N_NODES];
__device__ float    g_row_wsum[N_NODES];
__device__ int2     g_ell_cv[N_NODES * MAXD];
__device__ float    g_Wcomb[FEAT * G3];
__device__ float    g_bcomb[G3];
__device__ float    g_partN[64 * N_NODES];          // TRANSPOSED: [stat c][node n]
__device__ float    g_stat[64];                     // 0-31 sum, 32-63 sumsq
__device__ uint32_t g_xT2[(size_t)N_NODES * 16 * 32];  // [n][btp][f] half2=(bt, bt+16), 8MB
// ya as gru fragment words: [bt][node][f2], word = f16x2(f=2*f2, f=2*f2+1)
__device__ uint32_t g_yaH[(size_t)NBT * N_NODES * 16];   // 8MB

// ============================================================
// helpers
// ============================================================
__device__ __forceinline__ float sigm(float v) { return __fdividef(1.0f, 1.0f + __expf(-v)); }
__device__ __forceinline__ float tanh_fast(float v) {
    const float e = __expf(-2.0f * v);
    return __fdividef(1.0f - e, 1.0f + e);
}
// pack two floats to f16x2 (first arg -> low half)
__device__ __forceinline__ uint32_t pack_f16x2(float lo_val, float hi_val) {
    uint32_t r;
    asm("cvt.rn.f16x2.f32 %0, %1, %2;" : "=r"(r) : "f"(hi_val), "f"(lo_val));
    return r;
}
__device__ __forceinline__ void mma16(float* d, const uint4& a, const uint2& b) {
    asm volatile(
        "mma.sync.aligned.m16n8k16.row.col.f32.f16.f16.f32 "
        "{%0,%1,%2,%3}, {%4,%5,%6,%7}, {%8,%9}, {%0,%1,%2,%3};"
        : "+f"(d[0]), "+f"(d[1]), "+f"(d[2]), "+f"(d[3])
        : "r"(a.x), "r"(a.y), "r"(a.z), "r"(a.w), "r"(b.x), "r"(b.y));
}

// ============================================================
// Kernel 1 (fused prep): blocks [0,512)   -> dense adj -> packed ELL
//                        blocks [512,4608)-> transpose x (fp16x2) + BN partials
// ============================================================
__global__ void __launch_bounds__(256)
prep_kernel(const float* __restrict__ adj, const float* __restrict__ x)
{
    const int tid  = threadIdx.x;
    const int lane = tid & 31;
    const int w    = tid >> 5;

    if (blockIdx.x < 512) {
        // ---------- ELL build: warp = one adjacency row, MLP=8 ----------
        const int warp = blockIdx.x * 8 + w;
        const float* row = adj + (size_t)warp * N_NODES;
        const int base = warp * MAXD;
        int cnt = 0; float wsum = 0.f;
        #pragma unroll 1
        for (int g = 0; g < N_NODES / 256; ++g) {
            float v[8];
            #pragma unroll
            for (int j = 0; j < 8; ++j) v[j] = row[g * 256 + j * 32 + lane];
            #pragma unroll
            for (int j = 0; j < 8; ++j) {
                const int c = g * 256 + j * 32 + lane;
                wsum += v[j];
                const unsigned mask = __ballot_sync(0xffffffffu, v[j] != 0.0f);
                if (v[j] != 0.0f) {
                    const int pos = cnt + __popc(mask & ((1u << lane) - 1u));
                    if (pos < MAXD) g_ell_cv[base + pos] = make_int2(c, __float_as_int(v[j]));
                }
                cnt += __popc(mask);
            }
        }
        #pragma unroll
        for (int o = 16; o > 0; o >>= 1) wsum += __shfl_xor_sync(0xffffffffu, wsum, o);
        if (lane == 0) {
            g_row_len[warp]  = cnt < MAXD ? cnt : MAXD;
            g_row_wsum[warp] = wsum;
        }
    } else {
        // ---------- transpose to fp16x2 + per-node BN partials ----------
        const int n   = blockIdx.x - 512;
        const int bt  = tid >> 3;
        const int f0  = (tid & 7) * 4;

        __shared__ float sh[8][64];
        __shared__ float xbuf[32][32];

        const float4 v = *(const float4*)(x + ((size_t)bt * N_NODES + n) * FEAT + f0);
        *(float4*)&xbuf[bt][f0] = v;

        float s0 = v.x, s1 = v.y, s2 = v.z, s3 = v.w;
        float q0 = v.x * v.x, q1 = v.y * v.y, q2 = v.z * v.z, q3 = v.w * v.w;
        #pragma unroll
        for (int o = 8; o <= 16; o <<= 1) {
            s0 += __shfl_xor_sync(0xffffffffu, s0, o);
            s1 += __shfl_xor_sync(0xffffffffu, s1, o);
            s2 += __shfl_xor_sync(0xffffffffu, s2, o);
            s3 += __shfl_xor_sync(0xffffffffu, s3, o);
            q0 += __shfl_xor_sync(0xffffffffu, q0, o);
            q1 += __shfl_xor_sync(0xffffffffu, q1, o);
            q2 += __shfl_xor_sync(0xffffffffu, q2, o);
            q3 += __shfl_xor_sync(0xffffffffu, q3, o);
        }
        if (lane < 8) {
            sh[w][f0 + 0]      = s0;  sh[w][f0 + 1]      = s1;
            sh[w][f0 + 2]      = s2;  sh[w][f0 + 3]      = s3;
            sh[w][32 + f0 + 0] = q0;  sh[w][32 + f0 + 1] = q1;
            sh[w][32 + f0 + 2] = q2;  sh[w][32 + f0 + 3] = q3;
        }
        __syncthreads();
        if (tid < 64) {
            float a = 0.f;
            #pragma unroll
            for (int i = 0; i < 8; ++i) a += sh[i][tid];
            g_partN[tid * N_NODES + n] = a;     // transposed layout
        }
        if (tid < 128) {
            const int btp = tid >> 3;
            const int fq  = (tid & 7) * 4;
            const float4 a = *(const float4*)&xbuf[btp][fq];
            const float4 b = *(const float4*)&xbuf[btp + 16][fq];
            uint4 wv;
            wv.x = pack_f16x2(a.x, b.x);
            wv.y = pack_f16x2(a.y, b.y);
            wv.z = pack_f16x2(a.z, b.z);
            wv.w = pack_f16x2(a.w, b.w);
            *(uint4*)&g_xT2[((size_t)n * 16 + btp) * 32 + fq] = wv;
        }
    }
}

// ============================================================
// Kernel 2 (parallel finalize): blocks 0-63  -> stat column reduce
//                               blocks 64-87 -> Wcomb, block 88 -> bcomb
// ============================================================
__global__ void __launch_bounds__(256)
finalize_kernel(const float* __restrict__ Wgcn,
                const float* __restrict__ bgcn,
                const float* __restrict__ Wih,
                const float* __restrict__ bih)
{
    const int tid = threadIdx.x;
    const int bid = blockIdx.x;

    if (bid < 64) {
        __shared__ float red[256];
        const float* p = g_partN + bid * N_NODES;
        float a = 0.f;
        #pragma unroll 4
        for (int i = tid; i < N_NODES; i += 256) a += p[i];
        red[tid] = a;
        __syncthreads();
        #pragma unroll
        for (int s = 128; s > 0; s >>= 1) {
            if (tid < s) red[tid] += red[tid + s];
            __syncthreads();
        }
        if (tid == 0) g_stat[bid] = red[0];
    } else if (bid < 88) {
        const int idx = (bid - 64) * 256 + tid;   // < 6144
        const int f = idx / G3, j = idx % G3;
        float acc = 0.f;
        #pragma unroll 8
        for (int c = 0; c < 32; ++c) acc += Wgcn[f * 32 + c] * Wih[c * G3 + j];
        g_Wcomb[idx] = acc;
    } else {
        if (tid < G3) {
            float acc = bih[tid];
            #pragma unroll 8
            for (int c = 0; c < 32; ++c) acc += bgcn[c] * Wih[c * G3 + tid];
            g_bcomb[tid] = acc;
        }
    }
}

// ============================================================
// Kernel 3: aggregation (one block = one node, all 32 bt), fp16 x.
// thread = (feature-pair f2 = tid&15, btp = tid>>4 covering bt, bt+16).
// Output = gru fragment words, fp16 (single plane).
// ============================================================
__global__ void __launch_bounds__(256)
agg_kernel(const float* __restrict__ gamma, const float* __restrict__ beta)
{
    const int m   = blockIdx.x;
    const int tid = threadIdx.x;
    const int f2  = tid & 15;            // feature pair: f0 = 2*f2, f1 = 2*f2+1
    const int btp = tid >> 4;            // covers bt = btp and btp+16

    const int len = g_row_len[m];
    const float wsum = g_row_wsum[m];
    const int2* cv = g_ell_cv + m * MAXD;

    float a00 = 0.f, a01 = 0.f, a10 = 0.f, a11 = 0.f;
    const int off = btp * 32 + f2 * 2;

    int k = 0;
    for (; k + 3 < len; k += 4) {
        const int2 e0 = cv[k], e1 = cv[k + 1], e2 = cv[k + 2], e3 = cv[k + 3];
        const float w0 = __int_as_float(e0.y), w1 = __int_as_float(e1.y);
        const float w2 = __int_as_float(e2.y), w3 = __int_as_float(e3.y);
        const uint2 r0 = *(const uint2*)(g_xT2 + (size_t)e0.x * 512 + off);
        const uint2 r1 = *(const uint2*)(g_xT2 + (size_t)e1.x * 512 + off);
        const uint2 r2 = *(const uint2*)(g_xT2 + (size_t)e2.x * 512 + off);
        const uint2 r3 = *(const uint2*)(g_xT2 + (size_t)e3.x * 512 + off);
        {
            const float2 u0 = __half22float2(*(const __half2*)&r0.x);
            const float2 u1 = __half22float2(*(const __half2*)&r0.y);
            a00 += w0 * u0.x; a01 += w0 * u0.y; a10 += w0 * u1.x; a11 += w0 * u1.y;
        }
        {
            const float2 u0 = __half22float2(*(const __half2*)&r1.x);
            const float2 u1 = __half22float2(*(const __half2*)&r1.y);
            a00 += w1 * u0.x; a01 += w1 * u0.y; a10 += w1 * u1.x; a11 += w1 * u1.y;
        }
        {
            const float2 u0 = __half22float2(*(const __half2*)&r2.x);
            const float2 u1 = __half22float2(*(const __half2*)&r2.y);
            a00 += w2 * u0.x; a01 += w2 * u0.y; a10 += w2 * u1.x; a11 += w2 * u1.y;
        }
        {
            const float2 u0 = __half22float2(*(const __half2*)&r3.x);
            const float2 u1 = __half22float2(*(const __half2*)&r3.y);
            a00 += w3 * u0.x; a01 += w3 * u0.y; a10 += w3 * u1.x; a11 += w3 * u1.y;
        }
    }
    for (; k < len; ++k) {
        const int2 e = cv[k];
        const float w = __int_as_float(e.y);
        const uint2 r = *(const uint2*)(g_xT2 + (size_t)e.x * 512 + off);
        const float2 u0 = __half22float2(*(const __half2*)&r.x);
        const float2 u1 = __half22float2(*(const __half2*)&r.y);
        a00 += w * u0.x; a01 += w * u0.y; a10 += w * u1.x; a11 += w * u1.y;
    }

    const float M = (float)NROWS;
    const int f0i = 2 * f2, f1i = 2 * f2 + 1;
    const float mean0 = g_stat[f0i] / M;
    const float var0  = g_stat[32 + f0i] / M - mean0 * mean0;
    const float A0    = gamma[f0i] * rsqrtf(var0 + 1e-5f);
    const float C0    = (beta[f0i] - mean0 * A0) * wsum;
    const float mean1 = g_stat[f1i] / M;
    const float var1  = g_stat[32 + f1i] / M - mean1 * mean1;
    const float A1    = gamma[f1i] * rsqrtf(var1 + 1e-5f);
    const float C1    = (beta[f1i] - mean1 * A1) * wsum;

    const float y00 = A0 * a00 + C0;   // f0, bt=btp
    const float y10 = A1 * a10 + C1;   // f1, bt=btp
    const float y01 = A0 * a01 + C0;   // f0, bt=btp+16
    const float y11 = A1 * a11 + C1;   // f1, bt=btp+16

    const size_t o0 = ((size_t)btp * N_NODES + m) * 16 + f2;
    const size_t o1 = ((size_t)(btp + 16) * N_NODES + m) * 16 + f2;
    g_yaH[o0] = pack_f16x2(y00, y10);
    g_yaH[o1] = pack_f16x2(y01, y11);
}

// ============================================================
// Kernel 4: GRU scan via mma.sync m16n8k16, pure fp16 operands.
// block = 64 nodes x 1 batch, 256 threads, 2 blocks/SM, grid 256.
// 72 mma/warp/t; single A plane; fp32 accumulate.
// ============================================================
#define GK16(C, ACCN)                                                             \
{                                                                                 \
    const uint4 ah0 = *(const uint4*)&sAh[(((C) * 4 + mq * 2    ) * 32 + lane) * 4]; \
    const uint4 ah1 = *(const uint4*)&sAh[(((C) * 4 + mq * 2 + 1) * 32 + lane) * 4]; \
    _Pragma("unroll")                                                             \
    for (int tt = 0; tt < 6; ++tt) {                                              \
        const uint2 bh = *(const uint2*)&sB[(((C) * 24 + tbase + tt) * 32 + lane) * 2]; \
        float* c0p; float* c1p;                                                   \
        if (tt < 4) { c0p = accRZ[0][tt];     c1p = accRZ[1][tt];     }           \
        else        { c0p = ACCN[0][tt - 4];  c1p = ACCN[1][tt - 4];  }           \
        mma16(c0p, ah0, bh);                                                      \
        mma16(c1p, ah1, bh);                                                      \
    }                                                                             \
}

__global__ void __launch_bounds__(GT, 2)
gru_mma_kernel(const float* __restrict__ Whh,
               const float* __restrict__ bhh,
               const float* __restrict__ Wd,
               const float* __restrict__ bd,
               float* __restrict__ out)
{
    extern __shared__ float sm[];
    float* sB    = sm + O_B;
    float* sAh   = sm + O_AH;
    float* sBias = sm + O_BIAS;
    float* sWd   = sm + O_WD;
    float* sHead = sm + O_HEAD;

    const int tid  = threadIdx.x;
    const int wid  = tid >> 5;
    const int lane = tid & 31;
    const int mq   = wid >> 2;          // m-group 0..1 (m16 tiles mq*2, mq*2+1)
    const int q    = wid & 3;           // col-group 0..3 (hd in [q*16, q*16+16))
    const int tbase = q * 6;

    const int b   = blockIdx.x >> 6;
    const int gm0 = (blockIdx.x & 63) * NP;

    // ---- zero A fragment region (h0 = 0) ----
    for (int i = tid; i < 3072; i += GT) sAh[i] = 0.0f;

    // ---- stage B fragments (fp16, q-major tile order) ----
    {
        __half* pB = (__half*)sB;
        for (int idx = tid; idx < 96 * G3; idx += GT) {
            const int k = idx / G3, n = idx % G3;
            const float w = (k < 32) ? g_Wcomb[k * G3 + n] : Whh[(k - 32) * G3 + n];
            const __half hh = __float2half_rn(w);
            const int g    = n >> 6;
            const int hd   = n & 63;
            const int j    = hd >> 3;
            const int qq   = j >> 1;
            const int sub  = j & 1;
            const int tile = qq * 6 + g * 2 + sub;
            const int ccol = hd & 7;
            const int chunk = k >> 4;
            const int rem   = k & 15;
            const int lt    = ccol * 4 + ((rem & 7) >> 1);
            const int regB  = (rem >= 8) ? 1 : 0;
            const int hb    = rem & 1;
            const int base  = ((chunk * 24 + tile) * 32 + lt) * 2;
            pB[(base + regB) * 2 + hb] = hh;
        }
    }
    if (tid < HDIM) {
        sBias[tid]       = g_bcomb[tid]       + bhh[tid];        // r
        sBias[64 + tid]  = g_bcomb[64 + tid]  + bhh[64 + tid];   // z
        sBias[128 + tid] = g_bcomb[128 + tid];                   // n_i
        sBias[192 + tid] = bhh[128 + tid];                       // n_h
        sWd[tid]         = Wd[tid];
    }
    const float bdv = bd[0];

    // ---- epilogue geometry ----
    const int gr = lane >> 2;
    const int c0 = (lane & 3) * 2;

    float hprev[2][2][4];
    #pragma unroll
    for (int m = 0; m < 2; ++m)
        #pragma unroll
        for (int sub = 0; sub < 2; ++sub)
            #pragma unroll
            for (int s = 0; s < 4; ++s) hprev[m][sub][s] = 0.0f;

    // ---- ya staging geometry (word copy from pre-packed plane) ----
    const int nodeS = tid >> 2;           // 0..63
    const int fc    = tid & 3;            // word group: words fc*4 .. fc*4+3
    const int baseS = (((fc >> 1) * 4 + (nodeS >> 4)) * 32 + (nodeS & 7) * 4) * 4
                      + ((fc & 1) ? 2 : 0) + (((nodeS & 15) >= 8) ? 1 : 0);

    // ---- stage ya_0 ----
    {
        const size_t po = ((size_t)(b * TSTEPS) * N_NODES + gm0 + nodeS) * 16 + fc * 4;
        const uint4 hv = *(const uint4*)(g_yaH + po);
        sAh[baseS + 0]  = __uint_as_float(hv.x);
        sAh[baseS + 4]  = __uint_as_float(hv.y);
        sAh[baseS + 8]  = __uint_as_float(hv.z);
        sAh[baseS + 12] = __uint_as_float(hv.w);
    }
    __syncthreads();

    uint4 pfH;

    for (int t8 = 0; t8 < TSTEPS; ++t8) {
        // ---- accumulators ----
        float accRZ[2][4][4], accNi[2][2][4], accNh[2][2][4];
        #pragma unroll
        for (int m = 0; m < 2; ++m) {
            #pragma unroll
            for (int t = 0; t < 4; ++t)
                #pragma unroll
                for (int s = 0; s < 4; ++s) accRZ[m][t][s] = 0.0f;
            #pragma unroll
            for (int t = 0; t < 2; ++t)
                #pragma unroll
                for (int s = 0; s < 4; ++s) { accNi[m][t][s] = 0.0f; accNh[m][t][s] = 0.0f; }
        }

        GK16(0, accNi) GK16(1, accNi)
        GK16(2, accNh) GK16(3, accNh) GK16(4, accNh) GK16(5, accNh)

        // prefetch next ya during GEMM
        if (t8 + 1 < TSTEPS) {
            const size_t po = ((size_t)(b * TSTEPS + t8 + 1) * N_NODES + gm0 + nodeS) * 16 + fc * 4;
            pfH = *(const uint4*)(g_yaH + po);
        }
        __syncthreads();   // all warps done reading A frags (ya_t + h_t)

        // ---- register epilogue ----
        float hp[2][2] = {{0.f, 0.f}, {0.f, 0.f}};
        #pragma unroll
        for (int m = 0; m < 2; ++m) {
            #pragma unroll
            for (int sub = 0; sub < 2; ++sub) {
                float hv[4];
                #pragma unroll
                for (int s = 0; s < 4; ++s) {
                    const int hd = q * 16 + sub * 8 + c0 + (s & 1);
                    const float r = sigm(accRZ[m][sub][s]     + sBias[hd]);
                    const float z = sigm(accRZ[m][2 + sub][s] + sBias[64 + hd]);
                    const float n = tanh_fast(accNi[m][sub][s] + sBias[128 + hd]
                                              + r * (accNh[m][sub][s] + sBias[192 + hd]));
                    hv[s] = (1.0f - z) * n + z * hprev[m][sub][s];
                    hprev[m][sub][s] = hv[s];
                    hp[m][s >> 1] += hv[s] * sWd[hd];
                }
                // write h back into A fragments at k = 32 + q*16 + sub*8 + cc
                const int base = (((2 + q) * 4 + mq * 2 + m) * 32 + lane) * 4;
                sAh[base + sub * 2]     = __uint_as_float(pack_f16x2(hv[0], hv[1]));
                sAh[base + sub * 2 + 1] = __uint_as_float(pack_f16x2(hv[2], hv[3]));
            }
        }
        // stage ya_{t+1} (chunks 0-1, disjoint from h chunks 2-5): pure word copy
        if (t8 + 1 < TSTEPS) {
            sAh[baseS + 0]  = __uint_as_float(pfH.x);
            sAh[baseS + 4]  = __uint_as_float(pfH.y);
            sAh[baseS + 8]  = __uint_as_float(pfH.z);
            sAh[baseS + 12] = __uint_as_float(pfH.w);
        }
        // head reduce across the 4 lanes sharing gr
        #pragma unroll
        for (int m = 0; m < 2; ++m) {
            hp[m][0] += __shfl_xor_sync(0xffffffffu, hp[m][0], 1);
            hp[m][0] += __shfl_xor_sync(0xffffffffu, hp[m][0], 2);
            hp[m][1] += __shfl_xor_sync(0xffffffffu, hp[m][1], 1);
            hp[m][1] += __shfl_xor_sync(0xffffffffu, hp[m][1], 2);
        }
        if ((lane & 3) == 0) {
            #pragma unroll
            for (int m = 0; m < 2; ++m) {
                const int node = (mq * 2 + m) * 16 + gr;
                sHead[q * 64 + node]     = hp[m][0];
                sHead[q * 64 + node + 8] = hp[m][1];
            }
        }
        __syncthreads();   // h frags + ya frags + sHead complete

        if (tid < NP) {
            out[(size_t)(b * TSTEPS + t8) * N_NODES + gm0 + tid] =
                bdv + sHead[tid] + sHead[64 + tid] + sHead[128 + tid] + sHead[192 + tid];
        }
        // out STG overlaps the next iteration's GEMM (no barrier between).
    }
}

// ============================================================
// launch
// ============================================================
extern "C" void kernel_launch(void* const* d_in, const int* in_sizes, int n_in,
                              void* d_out, int out_size)
{
    const float* x     = (const float*)d_in[0];
    const float* adj   = (const float*)d_in[1];
    const float* gamma = (const float*)d_in[2];
    const float* beta  = (const float*)d_in[3];
    const float* Wgcn  = (const float*)d_in[4];
    const float* bgcn  = (const float*)d_in[5];
    const float* Wih   = (const float*)d_in[6];
    const float* Whh   = (const float*)d_in[7];
    const float* bih   = (const float*)d_in[8];
    const float* bhh   = (const float*)d_in[9];
    const float* Wd    = (const float*)d_in[10];
    const float* bd    = (const float*)d_in[11];
    float* out = (float*)d_out;

    const int smem_bytes = SM_FLOATS * (int)sizeof(float);   // 51456
    cudaFuncSetAttribute(gru_mma_kernel, cudaFuncAttributeMaxDynamicSharedMemorySize, smem_bytes);

    prep_kernel<<<512 + N_NODES, 256>>>(adj, x);
    finalize_kernel<<<89, 256>>>(Wgcn, bgcn, Wih, bih);
    agg_kernel<<<N_NODES, 256>>>(gamma, beta);
    gru_mma_kernel<<<BATCH * (N_NODES / NP), GT, smem_bytes>>>(Whh, bhh, Wd, bd, out);
}

// round 16
// speedup vs baseline: 2.0520x; 1.0223x over previous
#include <cuda_runtime.h>
#include <cuda_fp16.h>
#include <cstdint>

#define N_NODES 4096
#define FEAT    32
#define G3      192
#define HDIM    64
#define BATCH   4
#define TSTEPS  8
#define NBT     (BATCH*TSTEPS)           // 32
#define MAXD    128
#define NROWS   (NBT*N_NODES)            // 131072

// ---- gru mma kernel geometry ----
#define NP      64                        // nodes per block
#define GT      256                       // threads (8 warps = 2 m-groups x 4 col-groups)

// smem float offsets (gru) -- fp16 frags, A double-buffered
#define O_B     0                         // B frags [6 k16][24 tiles][32 lanes][2 words]
#define O_AH    9216                      // A frags x2 buffers [3072 each]
#define O_BIAS  15360                     // [256] r|z|ni|nh
#define O_WD    15616                     // [64]
#define O_HEAD  15680                     // [512] two buffers of 256
#define SM_FLOATS 16192                   // 64768 bytes

// -------- static device scratch --------
__device__ int      g_row_len[N_NODES];
__device__ float    g_row_wsum[N_NODES];
__device__ int2     g_ell_cv[N_NODES * MAXD];
__device__ float    g_Wcomb[FEAT * G3];
__device__ float    g_bcomb[G3];
__device__ float    g_partN[64 * N_NODES];          // TRANSPOSED: [stat c][node n]
__device__ float    g_stat[64];                     // 0-31 sum, 32-63 sumsq
__device__ uint32_t g_xT2[(size_t)N_NODES * 16 * 32];  // [n][btp][f] half2=(bt, bt+16), 8MB
// ya as gru fragment words: [bt][node][f2], word = f16x2(f=2*f2, f=2*f2+1)
__device__ uint32_t g_yaH[(size_t)NBT * N_NODES * 16];   // 8MB

// ============================================================
// helpers
// ============================================================
__device__ __forceinline__ float sigm(float v) { return __fdividef(1.0f, 1.0f + __expf(-v)); }
__device__ __forceinline__ float tanh_fast(float v) {
    const float e = __expf(-2.0f * v);
    return __fdividef(1.0f - e, 1.0f + e);
}
// pack two floats to f16x2 (first arg -> low half)
__device__ __forceinline__ uint32_t pack_f16x2(float lo_val, float hi_val) {
    uint32_t r;
    asm("cvt.rn.f16x2.f32 %0, %1, %2;" : "=r"(r) : "f"(hi_val), "f"(lo_val));
    return r;
}
__device__ __forceinline__ void mma16(float* d, const uint4& a, const uint2& b) {
    asm volatile(
        "mma.sync.aligned.m16n8k16.row.col.f32.f16.f16.f32 "
        "{%0,%1,%2,%3}, {%4,%5,%6,%7}, {%8,%9}, {%0,%1,%2,%3};"
        : "+f"(d[0]), "+f"(d[1]), "+f"(d[2]), "+f"(d[3])
        : "r"(a.x), "r"(a.y), "r"(a.z), "r"(a.w), "r"(b.x), "r"(b.y));
}

// ============================================================
// Kernel 1 (fused prep): blocks [0,512)   -> dense adj -> packed ELL
//                        blocks [512,4608)-> transpose x (fp16x2) + BN partials
// ============================================================
__global__ void __launch_bounds__(256)
prep_kernel(const float* __restrict__ adj, const float* __restrict__ x)
{
    const int tid  = threadIdx.x;
    const int lane = tid & 31;
    const int w    = tid >> 5;

    if (blockIdx.x < 512) {
        // ---------- ELL build: warp = one adjacency row, MLP=8 ----------
        const int warp = blockIdx.x * 8 + w;
        const float* row = adj + (size_t)warp * N_NODES;
        const int base = warp * MAXD;
        int cnt = 0; float wsum = 0.f;
        #pragma unroll 1
        for (int g = 0; g < N_NODES / 256; ++g) {
            float v[8];
            #pragma unroll
            for (int j = 0; j < 8; ++j) v[j] = row[g * 256 + j * 32 + lane];
            #pragma unroll
            for (int j = 0; j < 8; ++j) {
                const int c = g * 256 + j * 32 + lane;
                wsum += v[j];
                const unsigned mask = __ballot_sync(0xffffffffu, v[j] != 0.0f);
                if (v[j] != 0.0f) {
                    const int pos = cnt + __popc(mask & ((1u << lane) - 1u));
                    if (pos < MAXD) g_ell_cv[base + pos] = make_int2(c, __float_as_int(v[j]));
                }
                cnt += __popc(mask);
            }
        }
        #pragma unroll
        for (int o = 16; o > 0; o >>= 1) wsum += __shfl_xor_sync(0xffffffffu, wsum, o);
        if (lane == 0) {
            g_row_len[warp]  = cnt < MAXD ? cnt : MAXD;
            g_row_wsum[warp] = wsum;
        }
    } else {
        // ---------- transpose to fp16x2 + per-node BN partials ----------
        const int n   = blockIdx.x - 512;
        const int bt  = tid >> 3;
        const int f0  = (tid & 7) * 4;

        __shared__ float sh[8][64];
        __shared__ float xbuf[32][32];

        const float4 v = *(const float4*)(x + ((size_t)bt * N_NODES + n) * FEAT + f0);
        *(float4*)&xbuf[bt][f0] = v;

        float s0 = v.x, s1 = v.y, s2 = v.z, s3 = v.w;
        float q0 = v.x * v.x, q1 = v.y * v.y, q2 = v.z * v.z, q3 = v.w * v.w;
        #pragma unroll
        for (int o = 8; o <= 16; o <<= 1) {
            s0 += __shfl_xor_sync(0xffffffffu, s0, o);
            s1 += __shfl_xor_sync(0xffffffffu, s1, o);
            s2 += __shfl_xor_sync(0xffffffffu, s2, o);
            s3 += __shfl_xor_sync(0xffffffffu, s3, o);
            q0 += __shfl_xor_sync(0xffffffffu, q0, o);
            q1 += __shfl_xor_sync(0xffffffffu, q1, o);
            q2 += __shfl_xor_sync(0xffffffffu, q2, o);
            q3 += __shfl_xor_sync(0xffffffffu, q3, o);
        }
        if (lane < 8) {
            sh[w][f0 + 0]      = s0;  sh[w][f0 + 1]      = s1;
            sh[w][f0 + 2]      = s2;  sh[w][f0 + 3]      = s3;
            sh[w][32 + f0 + 0] = q0;  sh[w][32 + f0 + 1] = q1;
            sh[w][32 + f0 + 2] = q2;  sh[w][32 + f0 + 3] = q3;
        }
        __syncthreads();
        if (tid < 64) {
            float a = 0.f;
            #pragma unroll
            for (int i = 0; i < 8; ++i) a += sh[i][tid];
            g_partN[tid * N_NODES + n] = a;     // transposed layout
        }
        if (tid < 128) {
            const int btp = tid >> 3;
            const int fq  = (tid & 7) * 4;
            const float4 a = *(const float4*)&xbuf[btp][fq];
            const float4 b = *(const float4*)&xbuf[btp + 16][fq];
            uint4 wv;
            wv.x = pack_f16x2(a.x, b.x);
            wv.y = pack_f16x2(a.y, b.y);
            wv.z = pack_f16x2(a.z, b.z);
            wv.w = pack_f16x2(a.w, b.w);
            *(uint4*)&g_xT2[((size_t)n * 16 + btp) * 32 + fq] = wv;
        }
    }
}

// ============================================================
// Kernel 2 (parallel finalize): blocks 0-63  -> stat column reduce
//                               blocks 64-87 -> Wcomb, block 88 -> bcomb
// ============================================================
__global__ void __launch_bounds__(256)
finalize_kernel(const float* __restrict__ Wgcn,
                const float* __restrict__ bgcn,
                const float* __restrict__ Wih,
                const float* __restrict__ bih)
{
    const int tid = threadIdx.x;
    const int bid = blockIdx.x;

    if (bid < 64) {
        __shared__ float red[256];
        const float* p = g_partN + bid * N_NODES;
        float a = 0.f;
        #pragma unroll 4
        for (int i = tid; i < N_NODES; i += 256) a += p[i];
        red[tid] = a;
        __syncthreads();
        #pragma unroll
        for (int s = 128; s > 0; s >>= 1) {
            if (tid < s) red[tid] += red[tid + s];
            __syncthreads();
        }
        if (tid == 0) g_stat[bid] = red[0];
    } else if (bid < 88) {
        const int idx = (bid - 64) * 256 + tid;   // < 6144
        const int f = idx / G3, j = idx % G3;
        float acc = 0.f;
        #pragma unroll 8
        for (int c = 0; c < 32; ++c) acc += Wgcn[f * 32 + c] * Wih[c * G3 + j];
        g_Wcomb[idx] = acc;
    } else {
        if (tid < G3) {
            float acc = bih[tid];
            #pragma unroll 8
            for (int c = 0; c < 32; ++c) acc += bgcn[c] * Wih[c * G3 + tid];
            g_bcomb[tid] = acc;
        }
    }
}

// ============================================================
// Kernel 3: aggregation (one block = one node, all 32 bt), fp16 x.
// thread = (feature-pair f2 = tid&15, btp = tid>>4 covering bt, bt+16).
// Output = gru fragment words, fp16 (single plane).
// ============================================================
__global__ void __launch_bounds__(256)
agg_kernel(const float* __restrict__ gamma, const float* __restrict__ beta)
{
    const int m   = blockIdx.x;
    const int tid = threadIdx.x;
    const int f2  = tid & 15;            // feature pair: f0 = 2*f2, f1 = 2*f2+1
    const int btp = tid >> 4;            // covers bt = btp and btp+16

    const int len = g_row_len[m];
    const float wsum = g_row_wsum[m];
    const int2* cv = g_ell_cv + m * MAXD;

    float a00 = 0.f, a01 = 0.f, a10 = 0.f, a11 = 0.f;
    const int off = btp * 32 + f2 * 2;

    int k = 0;
    for (; k + 3 < len; k += 4) {
        const int2 e0 = cv[k], e1 = cv[k + 1], e2 = cv[k + 2], e3 = cv[k + 3];
        const float w0 = __int_as_float(e0.y), w1 = __int_as_float(e1.y);
        const float w2 = __int_as_float(e2.y), w3 = __int_as_float(e3.y);
        const uint2 r0 = *(const uint2*)(g_xT2 + (size_t)e0.x * 512 + off);
        const uint2 r1 = *(const uint2*)(g_xT2 + (size_t)e1.x * 512 + off);
        const uint2 r2 = *(const uint2*)(g_xT2 + (size_t)e2.x * 512 + off);
        const uint2 r3 = *(const uint2*)(g_xT2 + (size_t)e3.x * 512 + off);
        {
            const float2 u0 = __half22float2(*(const __half2*)&r0.x);
            const float2 u1 = __half22float2(*(const __half2*)&r0.y);
            a00 += w0 * u0.x; a01 += w0 * u0.y; a10 += w0 * u1.x; a11 += w0 * u1.y;
        }
        {
            const float2 u0 = __half22float2(*(const __half2*)&r1.x);
            const float2 u1 = __half22float2(*(const __half2*)&r1.y);
            a00 += w1 * u0.x; a01 += w1 * u0.y; a10 += w1 * u1.x; a11 += w1 * u1.y;
        }
        {
            const float2 u0 = __half22float2(*(const __half2*)&r2.x);
            const float2 u1 = __half22float2(*(const __half2*)&r2.y);
            a00 += w2 * u0.x; a01 += w2 * u0.y; a10 += w2 * u1.x; a11 += w2 * u1.y;
        }
        {
            const float2 u0 = __half22float2(*(const __half2*)&r3.x);
            const float2 u1 = __half22float2(*(const __half2*)&r3.y);
            a00 += w3 * u0.x; a01 += w3 * u0.y; a10 += w3 * u1.x; a11 += w3 * u1.y;
        }
    }
    for (; k < len; ++k) {
        const int2 e = cv[k];
        const float w = __int_as_float(e.y);
        const uint2 r = *(const uint2*)(g_xT2 + (size_t)e.x * 512 + off);
        const float2 u0 = __half22float2(*(const __half2*)&r.x);
        const float2 u1 = __half22float2(*(const __half2*)&r.y);
        a00 += w * u0.x; a01 += w * u0.y; a10 += w * u1.x; a11 += w * u1.y;
    }

    const float M = (float)NROWS;
    const int f0i = 2 * f2, f1i = 2 * f2 + 1;
    const float mean0 = g_stat[f0i] / M;
    const float var0  = g_stat[32 + f0i] / M - mean0 * mean0;
    const float A0    = gamma[f0i] * rsqrtf(var0 + 1e-5f);
    const float C0    = (beta[f0i] - mean0 * A0) * wsum;
    const float mean1 = g_stat[f1i] / M;
    const float var1  = g_stat[32 + f1i] / M - mean1 * mean1;
    const float A1    = gamma[f1i] * rsqrtf(var1 + 1e-5f);
    const float C1    = (beta[f1i] - mean1 * A1) * wsum;

    const float y00 = A0 * a00 + C0;   // f0, bt=btp
    const float y10 = A1 * a10 + C1;   // f1, bt=btp
    const float y01 = A0 * a01 + C0;   // f0, bt=btp+16
    const float y11 = A1 * a11 + C1;   // f1, bt=btp+16

    const size_t o0 = ((size_t)btp * N_NODES + m) * 16 + f2;
    const size_t o1 = ((size_t)(btp + 16) * N_NODES + m) * 16 + f2;
    g_yaH[o0] = pack_f16x2(y00, y10);
    g_yaH[o1] = pack_f16x2(y01, y11);
}

// ============================================================
// Kernel 4: GRU scan via mma.sync m16n8k16, pure fp16 operands,
// A fragments DOUBLE-BUFFERED -> ONE barrier per timestep.
// Per t: GEMM(reads buf p) -> epilogue(writes buf 1-p, sHead[p&1])
//        -> barrier -> out(reads sHead) + next GEMM.
// ============================================================
#define GK16(C, ACCN)                                                             \
{                                                                                 \
    const uint4 ah0 = *(const uint4*)&pA[(((C) * 4 + mq * 2    ) * 32 + lane) * 4]; \
    const uint4 ah1 = *(const uint4*)&pA[(((C) * 4 + mq * 2 + 1) * 32 + lane) * 4]; \
    _Pragma("unroll")                                                             \
    for (int tt = 0; tt < 6; ++tt) {                                              \
        const uint2 bh = *(const uint2*)&sB[(((C) * 24 + tbase + tt) * 32 + lane) * 2]; \
        float* c0p; float* c1p;                                                   \
        if (tt < 4) { c0p = accRZ[0][tt];     c1p = accRZ[1][tt];     }           \
        else        { c0p = ACCN[0][tt - 4];  c1p = ACCN[1][tt - 4];  }           \
        mma16(c0p, ah0, bh);                                                      \
        mma16(c1p, ah1, bh);                                                      \
    }                                                                             \
}

__global__ void __launch_bounds__(GT, 2)
gru_mma_kernel(const float* __restrict__ Whh,
               const float* __restrict__ bhh,
               const float* __restrict__ Wd,
               const float* __restrict__ bd,
               float* __restrict__ out)
{
    extern __shared__ float sm[];
    float* sB    = sm + O_B;
    float* sA0   = sm + O_AH;            // buffer 0
    float* sBias = sm + O_BIAS;
    float* sWd   = sm + O_WD;
    float* sHead = sm + O_HEAD;          // 2 x 256

    const int tid  = threadIdx.x;
    const int wid  = tid >> 5;
    const int lane = tid & 31;
    const int mq   = wid >> 2;          // m-group 0..1 (m16 tiles mq*2, mq*2+1)
    const int q    = wid & 3;           // col-group 0..3 (hd in [q*16, q*16+16))
    const int tbase = q * 6;

    const int b   = blockIdx.x >> 6;
    const int gm0 = (blockIdx.x & 63) * NP;

    // ---- zero both A fragment buffers (h0 = 0) ----
    for (int i = tid; i < 6144; i += GT) sA0[i] = 0.0f;

    // ---- stage B fragments (fp16, q-major tile order) ----
    {
        __half* pB = (__half*)sB;
        for (int idx = tid; idx < 96 * G3; idx += GT) {
            const int k = idx / G3, n = idx % G3;
            const float w = (k < 32) ? g_Wcomb[k * G3 + n] : Whh[(k - 32) * G3 + n];
            const __half hh = __float2half_rn(w);
            const int g    = n >> 6;
            const int hd   = n & 63;
            const int j    = hd >> 3;
            const int qq   = j >> 1;
            const int sub  = j & 1;
            const int tile = qq * 6 + g * 2 + sub;
            const int ccol = hd & 7;
            const int chunk = k >> 4;
            const int rem   = k & 15;
            const int lt    = ccol * 4 + ((rem & 7) >> 1);
            const int regB  = (rem >= 8) ? 1 : 0;
            const int hb    = rem & 1;
            const int base  = ((chunk * 24 + tile) * 32 + lt) * 2;
            pB[(base + regB) * 2 + hb] = hh;
        }
    }
    if (tid < HDIM) {
        sBias[tid]       = g_bcomb[tid]       + bhh[tid];        // r
        sBias[64 + tid]  = g_bcomb[64 + tid]  + bhh[64 + tid];   // z
        sBias[128 + tid] = g_bcomb[128 + tid];                   // n_i
        sBias[192 + tid] = bhh[128 + tid];                       // n_h
        sWd[tid]         = Wd[tid];
    }
    const float bdv = bd[0];

    // ---- epilogue geometry ----
    const int gr = lane >> 2;
    const int c0 = (lane & 3) * 2;

    float hprev[2][2][4];
    #pragma unroll
    for (int m = 0; m < 2; ++m)
        #pragma unroll
        for (int sub = 0; sub < 2; ++sub)
            #pragma unroll
            for (int s = 0; s < 4; ++s) hprev[m][sub][s] = 0.0f;

    // ---- ya staging geometry (word copy from pre-packed plane) ----
    const int nodeS = tid >> 2;           // 0..63
    const int fc    = tid & 3;            // word group: words fc*4 .. fc*4+3
    const int baseS = (((fc >> 1) * 4 + (nodeS >> 4)) * 32 + (nodeS & 7) * 4) * 4
                      + ((fc & 1) ? 2 : 0) + (((nodeS & 15) >= 8) ? 1 : 0);

    // ---- stage ya_0 into buffer 0 ----
    {
        const size_t po = ((size_t)(b * TSTEPS) * N_NODES + gm0 + nodeS) * 16 + fc * 4;
        const uint4 hv = *(const uint4*)(g_yaH + po);
        sA0[baseS + 0]  = __uint_as_float(hv.x);
        sA0[baseS + 4]  = __uint_as_float(hv.y);
        sA0[baseS + 8]  = __uint_as_float(hv.z);
        sA0[baseS + 12] = __uint_as_float(hv.w);
    }
    __syncthreads();

    uint4 pfH;

    for (int t8 = 0; t8 < TSTEPS; ++t8) {
        const int bo = (t8 & 1) * 3072;
        const float* pA = sA0 + bo;              // read buffer
        float* wA = sA0 + (bo ^ 3072);           // write buffer (next t)
        float* hOut = sHead + (t8 & 1) * 256;

        // ---- accumulators ----
        float accRZ[2][4][4], accNi[2][2][4], accNh[2][2][4];
        #pragma unroll
        for (int m = 0; m < 2; ++m) {
            #pragma unroll
            for (int t = 0; t < 4; ++t)
                #pragma unroll
                for (int s = 0; s < 4; ++s) accRZ[m][t][s] = 0.0f;
            #pragma unroll
            for (int t = 0; t < 2; ++t)
                #pragma unroll
                for (int s = 0; s < 4; ++s) { accNi[m][t][s] = 0.0f; accNh[m][t][s] = 0.0f; }
        }

        GK16(0, accNi) GK16(1, accNi)
        GK16(2, accNh) GK16(3, accNh) GK16(4, accNh) GK16(5, accNh)

        // prefetch next ya during GEMM
        if (t8 + 1 < TSTEPS) {
            const size_t po = ((size_t)(b * TSTEPS + t8 + 1) * N_NODES + gm0 + nodeS) * 16 + fc * 4;
            pfH = *(const uint4*)(g_yaH + po);
        }
        // NO barrier: epilogue writes go to the other buffer.

        // ---- register epilogue ----
        float hp[2][2] = {{0.f, 0.f}, {0.f, 0.f}};
        #pragma unroll
        for (int m = 0; m < 2; ++m) {
            #pragma unroll
            for (int sub = 0; sub < 2; ++sub) {
                float hv[4];
                #pragma unroll
                for (int s = 0; s < 4; ++s) {
                    const int hd = q * 16 + sub * 8 + c0 + (s & 1);
                    const float r = sigm(accRZ[m][sub][s]     + sBias[hd]);
                    const float z = sigm(accRZ[m][2 + sub][s] + sBias[64 + hd]);
                    const float n = tanh_fast(accNi[m][sub][s] + sBias[128 + hd]
                                              + r * (accNh[m][sub][s] + sBias[192 + hd]));
                    hv[s] = (1.0f - z) * n + z * hprev[m][sub][s];
                    hprev[m][sub][s] = hv[s];
                    hp[m][s >> 1] += hv[s] * sWd[hd];
                }
                // write h into NEXT buffer's A fragments at k = 32 + ...
                const int base = (((2 + q) * 4 + mq * 2 + m) * 32 + lane) * 4;
                wA[base + sub * 2]     = __uint_as_float(pack_f16x2(hv[0], hv[1]));
                wA[base + sub * 2 + 1] = __uint_as_float(pack_f16x2(hv[2], hv[3]));
            }
        }
        // stage ya_{t+1} into NEXT buffer (chunks 0-1)
        if (t8 + 1 < TSTEPS) {
            wA[baseS + 0]  = __uint_as_float(pfH.x);
            wA[baseS + 4]  = __uint_as_float(pfH.y);
            wA[baseS + 8]  = __uint_as_float(pfH.z);
            wA[baseS + 12] = __uint_as_float(pfH.w);
        }
        // head reduce across the 4 lanes sharing gr
        #pragma unroll
        for (int m = 0; m < 2; ++m) {
            hp[m][0] += __shfl_xor_sync(0xffffffffu, hp[m][0], 1);
            hp[m][0] += __shfl_xor_sync(0xffffffffu, hp[m][0], 2);
            hp[m][1] += __shfl_xor_sync(0xffffffffu, hp[m][1], 1);
            hp[m][1] += __shfl_xor_sync(0xffffffffu, hp[m][1], 2);
        }
        if ((lane & 3) == 0) {
            #pragma unroll
            for (int m = 0; m < 2; ++m) {
                const int node = (mq * 2 + m) * 16 + gr;
                hOut[q * 64 + node]     = hp[m][0];
                hOut[q * 64 + node + 8] = hp[m][1];
            }
        }
        __syncthreads();   // single barrier: h/ya frags (next buf) + sHead ready

        if (tid < NP) {
            out[(size_t)(b * TSTEPS + t8) * N_NODES + gm0 + tid] =
                bdv + hOut[tid] + hOut[64 + tid] + hOut[128 + tid] + hOut[192 + tid];
        }
        // out STG overlaps the next iteration's GEMM (no barrier between;
        // next epilogue writes the OTHER sHead buffer).
    }
}

// ============================================================
// launch
// ============================================================
extern "C" void kernel_launch(void* const* d_in, const int* in_sizes, int n_in,
                              void* d_out, int out_size)
{
    const float* x     = (const float*)d_in[0];
    const float* adj   = (const float*)d_in[1];
    const float* gamma = (const float*)d_in[2];
    const float* beta  = (const float*)d_in[3];
    const float* Wgcn  = (const float*)d_in[4];
    const float* bgcn  = (const float*)d_in[5];
    const float* Wih   = (const float*)d_in[6];
    const float* Whh   = (const float*)d_in[7];
    const float* bih   = (const float*)d_in[8];
    const float* bhh   = (const float*)d_in[9];
    const float* Wd    = (const float*)d_in[10];
    const float* bd    = (const float*)d_in[11];
    float* out = (float*)d_out;

    const int smem_bytes = SM_FLOATS * (int)sizeof(float);   // 64768
    cudaFuncSetAttribute(gru_mma_kernel, cudaFuncAttributeMaxDynamicSharedMemorySize, smem_bytes);

    prep_kernel<<<512 + N_NODES, 256>>>(adj, x);
    finalize_kernel<<<89, 256>>>(Wgcn, bgcn, Wih, bih);
    agg_kernel<<<N_NODES, 256>>>(gamma, beta);
    gru_mma_kernel<<<BATCH * (N_NODES / NP), GT, smem_bytes>>>(Whh, bhh, Wd, bd, out);
}

// round 17
// speedup vs baseline: 2.1020x; 1.0244x over previous
#include <cuda_runtime.h>
#include <cuda_fp16.h>
#include <cstdint>

#define N_NODES 4096
#define FEAT    32
#define G3      192
#define HDIM    64
#define BATCH   4
#define TSTEPS  8
#define NBT     (BATCH*TSTEPS)           // 32
#define MAXD    128
#define NROWS   (NBT*N_NODES)            // 131072

// ---- gru mma kernel geometry ----
#define NP      64                        // nodes per block
#define GT      256                       // threads (8 warps = 2 m-groups x 4 col-groups)

// smem float offsets (gru) -- fp16 frags, A double-buffered
#define O_B     0                         // B frags [6 k16][24 tiles][32 lanes][2 words]
#define O_AH    9216                      // A frags x2 buffers [3072 each]
#define O_BIAS  15360                     // [256] hbR|hbZ|bNi|hbNh
#define O_WD    15616                     // [64]
#define O_HEAD  15680                     // [512] two buffers of 256
#define SM_FLOATS 16192                   // 64768 bytes

// -------- static device scratch --------
__device__ int      g_row_len[N_NODES];
__device__ float    g_row_wsum[N_NODES];
__device__ int2     g_ell_cv[N_NODES * MAXD];
__device__ float    g_Wcomb[FEAT * G3];
__device__ float    g_bcomb[G3];
__device__ float    g_partN[64 * N_NODES];          // TRANSPOSED: [stat c][node n]
__device__ float    g_stat[64];                     // 0-31 sum, 32-63 sumsq
__device__ uint32_t g_xT2[(size_t)N_NODES * 16 * 32];  // [n][btp][f] half2=(bt, bt+16), 8MB
// ya as gru fragment words: [bt][node][f2], word = f16x2(f=2*f2, f=2*f2+1)
__device__ uint32_t g_yaH[(size_t)NBT * N_NODES * 16];   // 8MB

// ============================================================
// helpers
// ============================================================
__device__ __forceinline__ float tanh_hw(float v) {     // 1 MUFU (sigmoid gates only)
    float r;
    asm("tanh.approx.f32 %0, %1;" : "=f"(r) : "f"(v));
    return r;
}
__device__ __forceinline__ float tanh_fast(float v) {   // accurate path for n gate
    const float e = __expf(-2.0f * v);
    return __fdividef(1.0f - e, 1.0f + e);
}
// pack two floats to f16x2 (first arg -> low half)
__device__ __forceinline__ uint32_t pack_f16x2(float lo_val, float hi_val) {
    uint32_t r;
    asm("cvt.rn.f16x2.f32 %0, %1, %2;" : "=r"(r) : "f"(hi_val), "f"(lo_val));
    return r;
}
__device__ __forceinline__ void mma16(float* d, const uint4& a, const uint2& b) {
    asm volatile(
        "mma.sync.aligned.m16n8k16.row.col.f32.f16.f16.f32 "
        "{%0,%1,%2,%3}, {%4,%5,%6,%7}, {%8,%9}, {%0,%1,%2,%3};"
        : "+f"(d[0]), "+f"(d[1]), "+f"(d[2]), "+f"(d[3])
        : "r"(a.x), "r"(a.y), "r"(a.z), "r"(a.w), "r"(b.x), "r"(b.y));
}

// ============================================================
// Kernel 1 (fused prep): blocks [0,512)   -> dense adj -> packed ELL
//                        blocks [512,4608)-> transpose x (fp16x2) + BN partials
// ============================================================
__global__ void __launch_bounds__(256)
prep_kernel(const float* __restrict__ adj, const float* __restrict__ x)
{
    const int tid  = threadIdx.x;
    const int lane = tid & 31;
    const int w    = tid >> 5;

    if (blockIdx.x < 512) {
        // ---------- ELL build: warp = one adjacency row, MLP=8 ----------
        const int warp = blockIdx.x * 8 + w;
        const float* row = adj + (size_t)warp * N_NODES;
        const int base = warp * MAXD;
        int cnt = 0; float wsum = 0.f;
        #pragma unroll 1
        for (int g = 0; g < N_NODES / 256; ++g) {
            float v[8];
            #pragma unroll
            for (int j = 0; j < 8; ++j) v[j] = row[g * 256 + j * 32 + lane];
            #pragma unroll
            for (int j = 0; j < 8; ++j) {
                const int c = g * 256 + j * 32 + lane;
                wsum += v[j];
                const unsigned mask = __ballot_sync(0xffffffffu, v[j] != 0.0f);
                if (v[j] != 0.0f) {
                    const int pos = cnt + __popc(mask & ((1u << lane) - 1u));
                    if (pos < MAXD) g_ell_cv[base + pos] = make_int2(c, __float_as_int(v[j]));
                }
                cnt += __popc(mask);
            }
        }
        #pragma unroll
        for (int o = 16; o > 0; o >>= 1) wsum += __shfl_xor_sync(0xffffffffu, wsum, o);
        if (lane == 0) {
            g_row_len[warp]  = cnt < MAXD ? cnt : MAXD;
            g_row_wsum[warp] = wsum;
        }
    } else {
        // ---------- transpose to fp16x2 + per-node BN partials ----------
        const int n   = blockIdx.x - 512;
        const int bt  = tid >> 3;
        const int f0  = (tid & 7) * 4;

        __shared__ float sh[8][64];
        __shared__ float xbuf[32][32];

        const float4 v = *(const float4*)(x + ((size_t)bt * N_NODES + n) * FEAT + f0);
        *(float4*)&xbuf[bt][f0] = v;

        float s0 = v.x, s1 = v.y, s2 = v.z, s3 = v.w;
        float q0 = v.x * v.x, q1 = v.y * v.y, q2 = v.z * v.z, q3 = v.w * v.w;
        #pragma unroll
        for (int o = 8; o <= 16; o <<= 1) {
            s0 += __shfl_xor_sync(0xffffffffu, s0, o);
            s1 += __shfl_xor_sync(0xffffffffu, s1, o);
            s2 += __shfl_xor_sync(0xffffffffu, s2, o);
            s3 += __shfl_xor_sync(0xffffffffu, s3, o);
            q0 += __shfl_xor_sync(0xffffffffu, q0, o);
            q1 += __shfl_xor_sync(0xffffffffu, q1, o);
            q2 += __shfl_xor_sync(0xffffffffu, q2, o);
            q3 += __shfl_xor_sync(0xffffffffu, q3, o);
        }
        if (lane < 8) {
            sh[w][f0 + 0]      = s0;  sh[w][f0 + 1]      = s1;
            sh[w][f0 + 2]      = s2;  sh[w][f0 + 3]      = s3;
            sh[w][32 + f0 + 0] = q0;  sh[w][32 + f0 + 1] = q1;
            sh[w][32 + f0 + 2] = q2;  sh[w][32 + f0 + 3] = q3;
        }
        __syncthreads();
        if (tid < 64) {
            float a = 0.f;
            #pragma unroll
            for (int i = 0; i < 8; ++i) a += sh[i][tid];
            g_partN[tid * N_NODES + n] = a;     // transposed layout
        }
        if (tid < 128) {
            const int btp = tid >> 3;
            const int fq  = (tid & 7) * 4;
            const float4 a = *(const float4*)&xbuf[btp][fq];
            const float4 b = *(const float4*)&xbuf[btp + 16][fq];
            uint4 wv;
            wv.x = pack_f16x2(a.x, b.x);
            wv.y = pack_f16x2(a.y, b.y);
            wv.z = pack_f16x2(a.z, b.z);
            wv.w = pack_f16x2(a.w, b.w);
            *(uint4*)&g_xT2[((size_t)n * 16 + btp) * 32 + fq] = wv;
        }
    }
}

// ============================================================
// Kernel 2 (parallel finalize): blocks 0-63  -> stat column reduce
//                               blocks 64-87 -> Wcomb, block 88 -> bcomb
// ============================================================
__global__ void __launch_bounds__(256)
finalize_kernel(const float* __restrict__ Wgcn,
                const float* __restrict__ bgcn,
                const float* __restrict__ Wih,
                const float* __restrict__ bih)
{
    const int tid = threadIdx.x;
    const int bid = blockIdx.x;

    if (bid < 64) {
        __shared__ float red[256];
        const float* p = g_partN + bid * N_NODES;
        float a = 0.f;
        #pragma unroll 4
        for (int i = tid; i < N_NODES; i += 256) a += p[i];
        red[tid] = a;
        __syncthreads();
        #pragma unroll
        for (int s = 128; s > 0; s >>= 1) {
            if (tid < s) red[tid] += red[tid + s];
            __syncthreads();
        }
        if (tid == 0) g_stat[bid] = red[0];
    } else if (bid < 88) {
        const int idx = (bid - 64) * 256 + tid;   // < 6144
        const int f = idx / G3, j = idx % G3;
        float acc = 0.f;
        #pragma unroll 8
        for (int c = 0; c < 32; ++c) acc += Wgcn[f * 32 + c] * Wih[c * G3 + j];
        g_Wcomb[idx] = acc;
    } else {
        if (tid < G3) {
            float acc = bih[tid];
            #pragma unroll 8
            for (int c = 0; c < 32; ++c) acc += bgcn[c] * Wih[c * G3 + tid];
            g_bcomb[tid] = acc;
        }
    }
}

// ============================================================
// Kernel 3: aggregation (one block = one node, all 32 bt), fp16 x.
// thread = (feature-pair f2 = tid&15, btp = tid>>4 covering bt, bt+16).
// Output = gru fragment words, fp16 (single plane).
// ============================================================
__global__ void __launch_bounds__(256)
agg_kernel(const float* __restrict__ gamma, const float* __restrict__ beta)
{
    const int m   = blockIdx.x;
    const int tid = threadIdx.x;
    const int f2  = tid & 15;            // feature pair: f0 = 2*f2, f1 = 2*f2+1
    const int btp = tid >> 4;            // covers bt = btp and btp+16

    const int len = g_row_len[m];
    const float wsum = g_row_wsum[m];
    const int2* cv = g_ell_cv + m * MAXD;

    float a00 = 0.f, a01 = 0.f, a10 = 0.f, a11 = 0.f;
    const int off = btp * 32 + f2 * 2;

    int k = 0;
    for (; k + 3 < len; k += 4) {
        const int2 e0 = cv[k], e1 = cv[k + 1], e2 = cv[k + 2], e3 = cv[k + 3];
        const float w0 = __int_as_float(e0.y), w1 = __int_as_float(e1.y);
        const float w2 = __int_as_float(e2.y), w3 = __int_as_float(e3.y);
        const uint2 r0 = *(const uint2*)(g_xT2 + (size_t)e0.x * 512 + off);
        const uint2 r1 = *(const uint2*)(g_xT2 + (size_t)e1.x * 512 + off);
        const uint2 r2 = *(const uint2*)(g_xT2 + (size_t)e2.x * 512 + off);
        const uint2 r3 = *(const uint2*)(g_xT2 + (size_t)e3.x * 512 + off);
        {
            const float2 u0 = __half22float2(*(const __half2*)&r0.x);
            const float2 u1 = __half22float2(*(const __half2*)&r0.y);
            a00 += w0 * u0.x; a01 += w0 * u0.y; a10 += w0 * u1.x; a11 += w0 * u1.y;
        }
        {
            const float2 u0 = __half22float2(*(const __half2*)&r1.x);
            const float2 u1 = __half22float2(*(const __half2*)&r1.y);
            a00 += w1 * u0.x; a01 += w1 * u0.y; a10 += w1 * u1.x; a11 += w1 * u1.y;
        }
        {
            const float2 u0 = __half22float2(*(const __half2*)&r2.x);
            const float2 u1 = __half22float2(*(const __half2*)&r2.y);
            a00 += w2 * u0.x; a01 += w2 * u0.y; a10 += w2 * u1.x; a11 += w2 * u1.y;
        }
        {
            const float2 u0 = __half22float2(*(const __half2*)&r3.x);
            const float2 u1 = __half22float2(*(const __half2*)&r3.y);
            a00 += w3 * u0.x; a01 += w3 * u0.y; a10 += w3 * u1.x; a11 += w3 * u1.y;
        }
    }
    for (; k < len; ++k) {
        const int2 e = cv[k];
        const float w = __int_as_float(e.y);
        const uint2 r = *(const uint2*)(g_xT2 + (size_t)e.x * 512 + off);
        const float2 u0 = __half22float2(*(const __half2*)&r.x);
        const float2 u1 = __half22float2(*(const __half2*)&r.y);
        a00 += w * u0.x; a01 += w * u0.y; a10 += w * u1.x; a11 += w * u1.y;
    }

    const float M = (float)NROWS;
    const int f0i = 2 * f2, f1i = 2 * f2 + 1;
    const float mean0 = g_stat[f0i] / M;
    const float var0  = g_stat[32 + f0i] / M - mean0 * mean0;
    const float A0    = gamma[f0i] * rsqrtf(var0 + 1e-5f);
    const float C0    = (beta[f0i] - mean0 * A0) * wsum;
    const float mean1 = g_stat[f1i] / M;
    const float var1  = g_stat[32 + f1i] / M - mean1 * mean1;
    const float A1    = gamma[f1i] * rsqrtf(var1 + 1e-5f);
    const float C1    = (beta[f1i] - mean1 * A1) * wsum;

    const float y00 = A0 * a00 + C0;   // f0, bt=btp
    const float y10 = A1 * a10 + C1;   // f1, bt=btp
    const float y01 = A0 * a01 + C0;   // f0, bt=btp+16
    const float y11 = A1 * a11 + C1;   // f1, bt=btp+16

    const size_t o0 = ((size_t)btp * N_NODES + m) * 16 + f2;
    const size_t o1 = ((size_t)(btp + 16) * N_NODES + m) * 16 + f2;
    g_yaH[o0] = pack_f16x2(y00, y10);
    g_yaH[o1] = pack_f16x2(y01, y11);
}

// ============================================================
// Kernel 4: GRU scan via mma.sync m16n8k16, pure fp16 operands,
// A double-buffered, ONE barrier per timestep.
// Epilogue: sigmoid gates via tanh.approx (1 MUFU each, errors
// multiplicatively damped); n gate keeps accurate tanh.
// ============================================================
#define GK16(C, ACCN)                                                             \
{                                                                                 \
    const uint4 ah0 = *(const uint4*)&pA[(((C) * 4 + mq * 2    ) * 32 + lane) * 4]; \
    const uint4 ah1 = *(const uint4*)&pA[(((C) * 4 + mq * 2 + 1) * 32 + lane) * 4]; \
    _Pragma("unroll")                                                             \
    for (int tt = 0; tt < 6; ++tt) {                                              \
        const uint2 bh = *(const uint2*)&sB[(((C) * 24 + tbase + tt) * 32 + lane) * 2]; \
        float* c0p; float* c1p;                                                   \
        if (tt < 4) { c0p = accRZ[0][tt];     c1p = accRZ[1][tt];     }           \
        else        { c0p = ACCN[0][tt - 4];  c1p = ACCN[1][tt - 4];  }           \
        mma16(c0p, ah0, bh);                                                      \
        mma16(c1p, ah1, bh);                                                      \
    }                                                                             \
}

__global__ void __launch_bounds__(GT, 2)
gru_mma_kernel(const float* __restrict__ Whh,
               const float* __restrict__ bhh,
               const float* __restrict__ Wd,
               const float* __restrict__ bd,
               float* __restrict__ out)
{
    extern __shared__ float sm[];
    float* sB    = sm + O_B;
    float* sA0   = sm + O_AH;            // buffer 0
    float* sBias = sm + O_BIAS;
    float* sWd   = sm + O_WD;
    float* sHead = sm + O_HEAD;          // 2 x 256

    const int tid  = threadIdx.x;
    const int wid  = tid >> 5;
    const int lane = tid & 31;
    const int mq   = wid >> 2;          // m-group 0..1 (m16 tiles mq*2, mq*2+1)
    const int q    = wid & 3;           // col-group 0..3 (hd in [q*16, q*16+16))
    const int tbase = q * 6;

    const int b   = blockIdx.x >> 6;
    const int gm0 = (blockIdx.x & 63) * NP;

    // ---- zero both A fragment buffers (h0 = 0) ----
    for (int i = tid; i < 6144; i += GT) sA0[i] = 0.0f;

    // ---- stage B fragments (fp16, q-major tile order) ----
    {
        __half* pB = (__half*)sB;
        for (int idx = tid; idx < 96 * G3; idx += GT) {
            const int k = idx / G3, n = idx % G3;
            const float w = (k < 32) ? g_Wcomb[k * G3 + n] : Whh[(k - 32) * G3 + n];
            const __half hh = __float2half_rn(w);
            const int g    = n >> 6;
            const int hd   = n & 63;
            const int j    = hd >> 3;
            const int qq   = j >> 1;
            const int sub  = j & 1;
            const int tile = qq * 6 + g * 2 + sub;
            const int ccol = hd & 7;
            const int chunk = k >> 4;
            const int rem   = k & 15;
            const int lt    = ccol * 4 + ((rem & 7) >> 1);
            const int regB  = (rem >= 8) ? 1 : 0;
            const int hb    = rem & 1;
            const int base  = ((chunk * 24 + tile) * 32 + lt) * 2;
            pB[(base + regB) * 2 + hb] = hh;
        }
    }
    if (tid < HDIM) {
        sBias[tid]       = 0.5f * (g_bcomb[tid]      + bhh[tid]);       // half r bias
        sBias[64 + tid]  = 0.5f * (g_bcomb[64 + tid] + bhh[64 + tid]);  // half z bias
        sBias[128 + tid] = g_bcomb[128 + tid];                          // n_i bias
        sBias[192 + tid] = 0.5f * bhh[128 + tid];                       // half n_h bias
        sWd[tid]         = Wd[tid];
    }
    const float bdv = bd[0];

    // ---- epilogue geometry ----
    const int gr = lane >> 2;
    const int c0 = (lane & 3) * 2;

    float hprev[2][2][4];
    #pragma unroll
    for (int m = 0; m < 2; ++m)
        #pragma unroll
        for (int sub = 0; sub < 2; ++sub)
            #pragma unroll
            for (int s = 0; s < 4; ++s) hprev[m][sub][s] = 0.0f;

    // ---- ya staging geometry (word copy from pre-packed plane) ----
    const int nodeS = tid >> 2;           // 0..63
    const int fc    = tid & 3;            // word group: words fc*4 .. fc*4+3
    const int baseS = (((fc >> 1) * 4 + (nodeS >> 4)) * 32 + (nodeS & 7) * 4) * 4
                      + ((fc & 1) ? 2 : 0) + (((nodeS & 15) >= 8) ? 1 : 0);

    // ---- stage ya_0 into buffer 0 ----
    {
        const size_t po = ((size_t)(b * TSTEPS) * N_NODES + gm0 + nodeS) * 16 + fc * 4;
        const uint4 hv = *(const uint4*)(g_yaH + po);
        sA0[baseS + 0]  = __uint_as_float(hv.x);
        sA0[baseS + 4]  = __uint_as_float(hv.y);
        sA0[baseS + 8]  = __uint_as_float(hv.z);
        sA0[baseS + 12] = __uint_as_float(hv.w);
    }
    __syncthreads();

    uint4 pfH;

    for (int t8 = 0; t8 < TSTEPS; ++t8) {
        const int bo = (t8 & 1) * 3072;
        const float* pA = sA0 + bo;              // read buffer
        float* wA = sA0 + (bo ^ 3072);           // write buffer (next t)
        float* hOut = sHead + (t8 & 1) * 256;

        // ---- accumulators ----
        float accRZ[2][4][4], accNi[2][2][4], accNh[2][2][4];
        #pragma unroll
        for (int m = 0; m < 2; ++m) {
            #pragma unroll
            for (int t = 0; t < 4; ++t)
                #pragma unroll
                for (int s = 0; s < 4; ++s) accRZ[m][t][s] = 0.0f;
            #pragma unroll
            for (int t = 0; t < 2; ++t)
                #pragma unroll
                for (int s = 0; s < 4; ++s) { accNi[m][t][s] = 0.0f; accNh[m][t][s] = 0.0f; }
        }

        GK16(0, accNi) GK16(1, accNi)
        GK16(2, accNh) GK16(3, accNh) GK16(4, accNh) GK16(5, accNh)

        // prefetch next ya during GEMM
        if (t8 + 1 < TSTEPS) {
            const size_t po = ((size_t)(b * TSTEPS + t8 + 1) * N_NODES + gm0 + nodeS) * 16 + fc * 4;
            pfH = *(const uint4*)(g_yaH + po);
        }
        // NO barrier: epilogue writes go to the other buffer.

        // ---- register epilogue ----
        float hp[2][2] = {{0.f, 0.f}, {0.f, 0.f}};
        #pragma unroll
        for (int m = 0; m < 2; ++m) {
            #pragma unroll
            for (int sub = 0; sub < 2; ++sub) {
                float hv[4];
                #pragma unroll
                for (int s = 0; s < 4; ++s) {
                    const int hd = q * 16 + sub * 8 + c0 + (s & 1);
                    // r = 0.5*tanh(0.5*accR + hbR) + 0.5 (implicit)
                    const float tr  = tanh_hw(fmaf(0.5f, accRZ[m][sub][s],     sBias[hd]));
                    const float tz  = tanh_hw(fmaf(0.5f, accRZ[m][2 + sub][s], sBias[64 + hd]));
                    const float ghh = fmaf(0.5f, accNh[m][sub][s], sBias[192 + hd]);  // 0.5*gh_n
                    const float u   = accNi[m][sub][s] + sBias[128 + hd] + ghh;
                    const float n   = tanh_fast(fmaf(tr, ghh, u));  // gi_n + r*gh_n
                    const float d   = hprev[m][sub][s] - n;
                    hv[s] = fmaf(fmaf(tz, 0.5f, 0.5f), d, n);       // n + z*(h-n)
                    hprev[m][sub][s] = hv[s];
                    hp[m][s >> 1] += hv[s] * sWd[hd];
                }
                // write h into NEXT buffer's A fragments at k = 32 + ...
                const int base = (((2 + q) * 4 + mq * 2 + m) * 32 + lane) * 4;
                wA[base + sub * 2]     = __uint_as_float(pack_f16x2(hv[0], hv[1]));
                wA[base + sub * 2 + 1] = __uint_as_float(pack_f16x2(hv[2], hv[3]));
            }
        }
        // stage ya_{t+1} into NEXT buffer (chunks 0-1)
        if (t8 + 1 < TSTEPS) {
            wA[baseS + 0]  = __uint_as_float(pfH.x);
            wA[baseS + 4]  = __uint_as_float(pfH.y);
            wA[baseS + 8]  = __uint_as_float(pfH.z);
            wA[baseS + 12] = __uint_as_float(pfH.w);
        }
        // head reduce across the 4 lanes sharing gr
        #pragma unroll
        for (int m = 0; m < 2; ++m) {
            hp[m][0] += __shfl_xor_sync(0xffffffffu, hp[m][0], 1);
            hp[m][0] += __shfl_xor_sync(0xffffffffu, hp[m][0], 2);
            hp[m][1] += __shfl_xor_sync(0xffffffffu, hp[m][1], 1);
            hp[m][1] += __shfl_xor_sync(0xffffffffu, hp[m][1], 2);
        }
        if ((lane & 3) == 0) {
            #pragma unroll
            for (int m = 0; m < 2; ++m) {
                const int node = (mq * 2 + m) * 16 + gr;
                hOut[q * 64 + node]     = hp[m][0];
                hOut[q * 64 + node + 8] = hp[m][1];
            }
        }
        __syncthreads();   // single barrier: h/ya frags (next buf) + sHead ready

        if (tid < NP) {
            out[(size_t)(b * TSTEPS + t8) * N_NODES + gm0 + tid] =
                bdv + hOut[tid] + hOut[64 + tid] + hOut[128 + tid] + hOut[192 + tid];
        }
        // out STG overlaps the next iteration's GEMM.
    }
}

// ============================================================
// launch
// ============================================================
extern "C" void kernel_launch(void* const* d_in, const int* in_sizes, int n_in,
                              void* d_out, int out_size)
{
    const float* x     = (const float*)d_in[0];
    const float* adj   = (const float*)d_in[1];
    const float* gamma = (const float*)d_in[2];
    const float* beta  = (const float*)d_in[3];
    const float* Wgcn  = (const float*)d_in[4];
    const float* bgcn  = (const float*)d_in[5];
    const float* Wih   = (const float*)d_in[6];
    const float* Whh   = (const float*)d_in[7];
    const float* bih   = (const float*)d_in[8];
    const float* bhh   = (const float*)d_in[9];
    const float* Wd    = (const float*)d_in[10];
    const float* bd    = (const float*)d_in[11];
    float* out = (float*)d_out;

    const int smem_bytes = SM_FLOATS * (int)sizeof(float);   // 64768
    cudaFuncSetAttribute(gru_mma_kernel, cudaFuncAttributeMaxDynamicSharedMemorySize, smem_bytes);

    prep_kernel<<<512 + N_NODES, 256>>>(adj, x);
    finalize_kernel<<<89, 256>>>(Wgcn, bgcn, Wih, bih);
    agg_kernel<<<N_NODES, 256>>>(gamma, beta);
    gru_mma_kernel<<<BATCH * (N_NODES / NP), GT, smem_bytes>>>(Whh, bhh, Wd, bd, out);
}